// round 1
// baseline (speedup 1.0000x reference)
#include <cuda_runtime.h>
#include <math.h>

#define BB 4
#define CC 256
#define HH 64
#define WWI 64
#define NG 16384            // B*H*W
#define KD 2304             // C*9
#define WSZ (256*256*9)
#define OFFN (18*16384)     // elements of offset tensors / rp outputs

// ---------------- scratch (device globals; no allocation) ----------------
__device__ float g_col[(size_t)KD * NG];   // 151 MB im2col buffer
__device__ float g_bufA[(size_t)CC * NG];
__device__ float g_bufB[(size_t)CC * NG];
__device__ float g_loc[(size_t)CC * NG];
__device__ float g_cls[(size_t)CC * NG];
__device__ float g_nh[(size_t)CC * NG];    // NHWC copy for deform gathers
__device__ float g_off1[OFFN];
__device__ float g_off2[OFFN];

// ---------------- packed f32x2 helpers ----------------
__device__ __forceinline__ unsigned long long pack2(float x, float y) {
    unsigned long long r;
    asm("mov.b64 %0, {%1,%2};" : "=l"(r) : "f"(x), "f"(y));
    return r;
}
__device__ __forceinline__ void unpack2(unsigned long long v, float &x, float &y) {
    asm("mov.b64 {%0,%1}, %2;" : "=f"(x), "=f"(y) : "l"(v));
}
__device__ __forceinline__ unsigned long long ffma2(unsigned long long a,
                                                    unsigned long long b,
                                                    unsigned long long c) {
    unsigned long long d;
    asm("fma.rn.f32x2 %0, %1, %2, %3;" : "=l"(d) : "l"(a), "l"(b), "l"(c));
    return d;
}

// ---------------- im2col (regular conv, zero pad 1) ----------------
// col[(c*9+kk)][n], n = b*4096 + i*64 + j. One thread = 4 consecutive n.
__global__ __launch_bounds__(256) void im2col_k(const float* __restrict__ in,
                                                float* __restrict__ col) {
    int idx = blockIdx.x * 256 + threadIdx.x;      // < KD*4096
    int n = (idx & 4095) * 4;
    int r = idx >> 12;                             // 0..2303
    int c = r / 9;
    int kk = r - c * 9;
    int dy = kk / 3 - 1;
    int dx = kk - (kk / 3) * 3 - 1;
    int b = n >> 12;
    int ij = n & 4095;
    int i = ij >> 6, j = ij & 63;
    int y = i + dy;
    float4 v = make_float4(0.f, 0.f, 0.f, 0.f);
    if ((unsigned)y < 64u) {
        const float* row = in + (((size_t)b * CC + c) * 64 + y) * 64;
        int x = j + dx;
        v.x = ((unsigned)(x + 0) < 64u) ? row[x + 0] : 0.f;
        v.y = ((unsigned)(x + 1) < 64u) ? row[x + 1] : 0.f;
        v.z = ((unsigned)(x + 2) < 64u) ? row[x + 2] : 0.f;
        v.w = ((unsigned)(x + 3) < 64u) ? row[x + 3] : 0.f;
    }
    *(float4*)&col[(size_t)r * NG + n] = v;
}

// ---------------- SGEMM: C[m][n] = sum_k A[m][k]*B[k][n] ----------------
// A: [M][KD] row-major (weights). B: col [KD][NG]. Output written NCHW:
// out[b*bstride + m*4096 + ij], n = b*4096+ij.
// 128x128 tile, KT=8, 256 threads, 8x8 per thread via packed f32x2 FMA.
__global__ __launch_bounds__(256) void sgemm_k(const float* __restrict__ A,
                                               const float* __restrict__ B,
                                               float* __restrict__ C,
                                               int M, int bstride) {
    __shared__ __align__(16) float As[8][128];
    __shared__ __align__(16) float Bs[8][128];

    int tid = threadIdx.x;
    int n0 = blockIdx.x * 128;
    int m0 = blockIdx.y * 128;

    int arow = m0 + (tid >> 1);
    int arow_l = tid >> 1;
    int acol = (tid & 1) * 4;
    int brow = tid >> 5;
    int bcol = (tid & 31) * 4;

    int ty = tid >> 4;      // 0..15 -> rows ty*8..+7
    int tx = tid & 15;      // 0..15 -> cols tx*8..+7

    unsigned long long acc[8][4];
#pragma unroll
    for (int i = 0; i < 8; i++)
#pragma unroll
        for (int jj = 0; jj < 4; jj++) acc[i][jj] = 0ull;

    float4 afr = make_float4(0.f, 0.f, 0.f, 0.f);
    if (arow < M) afr = *(const float4*)(A + (size_t)arow * KD + acol);
    float4 bfr = *(const float4*)(B + (size_t)brow * NG + n0 + bcol);

    for (int k0 = 0; k0 < KD; k0 += 8) {
        As[acol + 0][arow_l] = afr.x;
        As[acol + 1][arow_l] = afr.y;
        As[acol + 2][arow_l] = afr.z;
        As[acol + 3][arow_l] = afr.w;
        *(float4*)&Bs[brow][bcol] = bfr;
        __syncthreads();

        int kn = k0 + 8;
        float4 nafr = afr, nbfr = bfr;
        if (kn < KD) {
            nafr = make_float4(0.f, 0.f, 0.f, 0.f);
            if (arow < M) nafr = *(const float4*)(A + (size_t)arow * KD + kn + acol);
            nbfr = *(const float4*)(B + (size_t)(kn + brow) * NG + n0 + bcol);
        }

#pragma unroll
        for (int kk = 0; kk < 8; kk++) {
            float4 a0 = *(const float4*)&As[kk][ty * 8];
            float4 a1 = *(const float4*)&As[kk][ty * 8 + 4];
            ulonglong2 bA = *(const ulonglong2*)&Bs[kk][tx * 8];
            ulonglong2 bBv = *(const ulonglong2*)&Bs[kk][tx * 8 + 4];
            unsigned long long b2[4] = {bA.x, bA.y, bBv.x, bBv.y};
            unsigned long long a2[8];
            a2[0] = pack2(a0.x, a0.x);
            a2[1] = pack2(a0.y, a0.y);
            a2[2] = pack2(a0.z, a0.z);
            a2[3] = pack2(a0.w, a0.w);
            a2[4] = pack2(a1.x, a1.x);
            a2[5] = pack2(a1.y, a1.y);
            a2[6] = pack2(a1.z, a1.z);
            a2[7] = pack2(a1.w, a1.w);
#pragma unroll
            for (int i = 0; i < 8; i++)
#pragma unroll
                for (int jj = 0; jj < 4; jj++)
                    acc[i][jj] = ffma2(a2[i], b2[jj], acc[i][jj]);
        }
        __syncthreads();
        afr = nafr;
        bfr = nbfr;
    }

    int b = n0 >> 12;
    int ijb = n0 & 4095;
#pragma unroll
    for (int i = 0; i < 8; i++) {
        int m = m0 + ty * 8 + i;
        if (m < M) {
            float* po = C + (size_t)b * bstride + (size_t)m * 4096 + ijb + tx * 8;
#pragma unroll
            for (int jj = 0; jj < 4; jj++) {
                float lo, hi;
                unpack2(acc[i][jj], lo, hi);
                float2 w2 = make_float2(lo, hi);
                *(float2*)(po + 2 * jj) = w2;
            }
        }
    }
}

// ---------------- GroupNorm: one block per (b, group) ----------------
__global__ __launch_bounds__(256) void groupnorm_k(const float* __restrict__ in,
                                                   float* __restrict__ out,
                                                   const float* __restrict__ gamma,
                                                   const float* __restrict__ beta) {
    int bg = blockIdx.x;
    int b = bg >> 5;
    int g = bg & 31;
    int tid = threadIdx.x;
    const float* p = in + ((size_t)b * CC + g * 8) * 4096;
    float s = 0.f, s2 = 0.f;
    for (int idx = tid; idx < 32768; idx += 256) {
        float v = p[idx];
        s += v;
        s2 += v * v;
    }
    __shared__ float sA[256], sB[256];
    sA[tid] = s;
    sB[tid] = s2;
    __syncthreads();
    for (int st = 128; st > 0; st >>= 1) {
        if (tid < st) { sA[tid] += sA[tid + st]; sB[tid] += sB[tid + st]; }
        __syncthreads();
    }
    __shared__ float sm, sr;
    if (tid == 0) {
        float mean = sA[0] * (1.f / 32768.f);
        float var = sB[0] * (1.f / 32768.f) - mean * mean;
        sm = mean;
        sr = rsqrtf(var + 1e-5f);
    }
    __syncthreads();
    float mean = sm, rstd = sr;
    float* o = out + ((size_t)b * CC + g * 8) * 4096;
    for (int idx = tid; idx < 32768; idx += 256) {
        int ch = g * 8 + (idx >> 12);
        o[idx] = (p[idx] - mean) * rstd * gamma[ch] + beta[ch];
    }
}

// ---------------- NCHW -> NHWC transpose (per batch) ----------------
__global__ void nchw2nhwc_k(const float* __restrict__ in, float* __restrict__ out) {
    __shared__ float t[32][33];
    int b = blockIdx.z;
    int hw0 = blockIdx.x * 32;
    int c0 = blockIdx.y * 32;
    int tx = threadIdx.x, ty = threadIdx.y;
    for (int r = ty; r < 32; r += 8)
        t[r][tx] = in[(size_t)b * CC * 4096 + (size_t)(c0 + r) * 4096 + hw0 + tx];
    __syncthreads();
    for (int r = ty; r < 32; r += 8)
        out[(size_t)b * 4096 * CC + (size_t)(hw0 + r) * CC + c0 + tx] = t[tx][r];
}

// ---------------- deformable im2col (bilinear, torchvision v1 semantics) ----
// One warp per output pixel n; channels coalesced from the NHWC copy.
__global__ __launch_bounds__(256) void deform_im2col_k(const float* __restrict__ nhwc,
                                                       const float* __restrict__ off,
                                                       float* __restrict__ col) {
    int warp = (blockIdx.x * 256 + threadIdx.x) >> 5;
    int lane = threadIdx.x & 31;
    if (warp >= NG) return;
    int n = warp;
    int b = n >> 12;
    int ij = n & 4095;
    int i = ij >> 6, j = ij & 63;
    const float* offb = off + (size_t)b * 18 * 4096 + ij;
#pragma unroll
    for (int k = 0; k < 9; k++) {
        float dy = offb[(size_t)(2 * k) << 12];
        float dx = offb[(size_t)(2 * k + 1) << 12];
        float y = dy + (float)(i - 1 + k / 3);
        float x = dx + (float)(j - 1 + k % 3);
        float y0f = floorf(y), x0f = floorf(x);
        int y0 = (int)y0f, x0 = (int)x0f;
        float wy = y - y0f, wx = x - x0f;
        bool vy0 = (unsigned)y0 < 64u;
        bool vy1 = (unsigned)(y0 + 1) < 64u;
        bool vx0 = (unsigned)x0 < 64u;
        bool vx1 = (unsigned)(x0 + 1) < 64u;
        float w00 = (vy0 && vx0) ? (1.f - wy) * (1.f - wx) : 0.f;
        float w01 = (vy0 && vx1) ? (1.f - wy) * wx : 0.f;
        float w10 = (vy1 && vx0) ? wy * (1.f - wx) : 0.f;
        float w11 = (vy1 && vx1) ? wy * wx : 0.f;
        int cy0 = min(max(y0, 0), 63), cy1 = min(max(y0 + 1, 0), 63);
        int cx0 = min(max(x0, 0), 63), cx1 = min(max(x0 + 1, 0), 63);
        const float* p00 = nhwc + (((size_t)b * 64 + cy0) * 64 + cx0) * CC;
        const float* p01 = nhwc + (((size_t)b * 64 + cy0) * 64 + cx1) * CC;
        const float* p10 = nhwc + (((size_t)b * 64 + cy1) * 64 + cx0) * CC;
        const float* p11 = nhwc + (((size_t)b * 64 + cy1) * 64 + cx1) * CC;
#pragma unroll
        for (int it = 0; it < 8; it++) {
            int c = lane + it * 32;
            float v = w00 * p00[c] + w01 * p01[c] + w10 * p10[c] + w11 * p11[c];
            col[(size_t)(c * 9 + k) * NG + n] = v;
        }
    }
}

// ---------------- rep-points epilogue ----------------
__global__ __launch_bounds__(256) void reppoints_k(const float* __restrict__ off1,
                                                   const float* __restrict__ off2,
                                                   float* __restrict__ out) {
    int idx = blockIdx.x * 256 + threadIdx.x;
    if (idx >= OFFN) return;
    int rem = idx % 73728;              // 18*4096
    int ch = rem >> 12;
    int ij = rem & 4095;
    int i = ij >> 6, j = ij & 63;
    int k = ch >> 1;
    float init = (ch & 1) ? (float)(j + (k % 3) - 1) : (float)(i + (k / 3) - 1);
    float r1 = init + off1[idx];
    out[idx] = r1;
    out[OFFN + idx] = r1 + off2[idx];
}

// ---------------- host orchestration ----------------
static void conv_step(const float* in, const float* w, float* col, float* outbuf,
                      int M, int bstride) {
    im2col_k<<<36864, 256>>>(in, col);
    dim3 grid(128, (M + 127) / 128);
    sgemm_k<<<grid, 256>>>(w, col, outbuf, M, bstride);
}

extern "C" void kernel_launch(void* const* d_in, const int* in_sizes, int n_in,
                              void* d_out, int out_size) {
    const float* feature = (const float*)d_in[0];
    const float* loc_ws  = (const float*)d_in[1];
    const float* loc_g   = (const float*)d_in[2];
    const float* loc_b   = (const float*)d_in[3];
    const float* cls_ws  = (const float*)d_in[4];
    const float* cls_g   = (const float*)d_in[5];
    const float* cls_b   = (const float*)d_in[6];
    const float* pi_w    = (const float*)d_in[7];
    const float* pio_w   = (const float*)d_in[8];
    const float* prd_w   = (const float*)d_in[9];
    const float* pro_w   = (const float*)d_in[10];
    const float* cd_w    = (const float*)d_in[11];
    const float* co_w    = (const float*)d_in[12];
    float* out = (float*)d_out;

    float *col, *bufA, *bufB, *loc, *cls, *nh, *off1, *off2;
    cudaGetSymbolAddress((void**)&col,  g_col);
    cudaGetSymbolAddress((void**)&bufA, g_bufA);
    cudaGetSymbolAddress((void**)&bufB, g_bufB);
    cudaGetSymbolAddress((void**)&loc,  g_loc);
    cudaGetSymbolAddress((void**)&cls,  g_cls);
    cudaGetSymbolAddress((void**)&nh,   g_nh);
    cudaGetSymbolAddress((void**)&off1, g_off1);
    cudaGetSymbolAddress((void**)&off2, g_off2);

    // loc subnet: 3x (conv + GN)
    conv_step(feature, loc_ws + 0 * WSZ, col, bufA, 256, 256 * 4096);
    groupnorm_k<<<128, 256>>>(bufA, bufB, loc_g + 0, loc_b + 0);
    conv_step(bufB, loc_ws + 1 * WSZ, col, bufA, 256, 256 * 4096);
    groupnorm_k<<<128, 256>>>(bufA, bufB, loc_g + 256, loc_b + 256);
    conv_step(bufB, loc_ws + 2 * WSZ, col, bufA, 256, 256 * 4096);
    groupnorm_k<<<128, 256>>>(bufA, loc, loc_g + 512, loc_b + 512);

    // cls subnet
    conv_step(feature, cls_ws + 0 * WSZ, col, bufA, 256, 256 * 4096);
    groupnorm_k<<<128, 256>>>(bufA, bufB, cls_g + 0, cls_b + 0);
    conv_step(bufB, cls_ws + 1 * WSZ, col, bufA, 256, 256 * 4096);
    groupnorm_k<<<128, 256>>>(bufA, bufB, cls_g + 256, cls_b + 256);
    conv_step(bufB, cls_ws + 2 * WSZ, col, bufA, 256, 256 * 4096);
    groupnorm_k<<<128, 256>>>(bufA, cls, cls_g + 512, cls_b + 512);

    // offset1 = conv(conv(loc, pi_w), pio_w)
    conv_step(loc, pi_w, col, bufA, 256, 256 * 4096);
    conv_step(bufA, pio_w, col, off1, 18, 18 * 4096);

    // offset2 = conv(deform_conv(loc, offset1, prd_w), pro_w)
    nchw2nhwc_k<<<dim3(128, 8, 4), dim3(32, 8)>>>(loc, nh);
    deform_im2col_k<<<2048, 256>>>(nh, off1, col);
    sgemm_k<<<dim3(128, 2), 256>>>(prd_w, col, bufA, 256, 256 * 4096);
    conv_step(bufA, pro_w, col, off2, 18, 18 * 4096);

    // classification = conv(deform_conv(cls, offset1, cd_w), co_w)
    nchw2nhwc_k<<<dim3(128, 8, 4), dim3(32, 8)>>>(cls, nh);
    deform_im2col_k<<<2048, 256>>>(nh, off1, col);
    sgemm_k<<<dim3(128, 2), 256>>>(cd_w, col, bufA, 256, 256 * 4096);
    conv_step(bufA, co_w, col, out + 2 * OFFN, 15, 15 * 4096);

    // rp1 / rp2
    reppoints_k<<<(OFFN + 255) / 256, 256>>>(off1, off2, out);
}

// round 3
// speedup vs baseline: 1.8014x; 1.8014x over previous
#include <cuda_runtime.h>
#include <cuda_bf16.h>
#include <cstdint>
#include <math.h>

#define NG 16384
#define OFFN (18*16384)
#define KDIM 6912           // logical split-K (9 kk * 3 seg * 256 c)
#define KSTORE 4608         // stored col K (seg2 dedups to seg0)
#define NCHUNK 108          // KDIM/64
#define WSZ (256*256*9)
#define GEMM_SMEM 66560     // 2 stages * (16KB A + 16KB B) + 1KB align pad

// ---------------- scratch (device globals; no allocation) ----------------
__device__ __nv_bfloat16 g_wa[(size_t)256*KDIM];
__device__ __nv_bfloat16 g_fhi[(size_t)NG*256];
__device__ __nv_bfloat16 g_flo[(size_t)NG*256];
__device__ __nv_bfloat16 g_thi[(size_t)NG*256];
__device__ __nv_bfloat16 g_tlo[(size_t)NG*256];
__device__ float g_nh1[(size_t)NG*256];
__device__ float g_nh2[(size_t)NG*256];
__device__ float g_bufA[(size_t)NG*256];
__device__ float g_bufB[(size_t)NG*256];
__device__ __nv_bfloat16 g_colb[(size_t)NG*KSTORE];
__device__ float g_off1[OFFN];
__device__ float g_off2[OFFN];

// ---------------- PTX helpers ----------------
__device__ __forceinline__ uint32_t smem_u32(const void* p) {
    uint32_t a;
    asm("{ .reg .u64 t; cvta.to.shared.u64 t, %1; cvt.u32.u64 %0, t; }" : "=r"(a) : "l"(p));
    return a;
}
#define SWZ(o) ((o) ^ (((o) >> 3) & 0x70))

__device__ __forceinline__ void cp16(uint32_t dst, const void* src, int ss) {
    asm volatile("cp.async.cg.shared.global [%0], [%1], 16, %2;\n" :: "r"(dst), "l"(src), "r"(ss));
}
__device__ __forceinline__ void cp_commit() { asm volatile("cp.async.commit_group;\n" ::: "memory"); }
__device__ __forceinline__ void cp_wait0()  { asm volatile("cp.async.wait_group 0;\n" ::: "memory"); }
__device__ __forceinline__ void cp_wait1()  { asm volatile("cp.async.wait_group 1;\n" ::: "memory"); }

__device__ __forceinline__ void ldm4(uint32_t* r, uint32_t addr) {
    asm volatile("ldmatrix.sync.aligned.m8n8.x4.shared.b16 {%0,%1,%2,%3}, [%4];"
        : "=r"(r[0]), "=r"(r[1]), "=r"(r[2]), "=r"(r[3]) : "r"(addr));
}
__device__ __forceinline__ void mma16816(float* d, const uint32_t* a, const uint32_t* b) {
    asm volatile("mma.sync.aligned.m16n8k16.row.col.f32.bf16.bf16.f32 "
        "{%0,%1,%2,%3}, {%4,%5,%6,%7}, {%8,%9}, {%0,%1,%2,%3};"
        : "+f"(d[0]), "+f"(d[1]), "+f"(d[2]), "+f"(d[3])
        : "r"(a[0]), "r"(a[1]), "r"(a[2]), "r"(a[3]), "r"(b[0]), "r"(b[1]));
}

// ---------------- weight convert: fp32 [M][256][3][3] -> bf16 A[256][6912] ----
__global__ __launch_bounds__(256) void wconv_k(const float* __restrict__ w,
                                               __nv_bfloat16* __restrict__ A, int M) {
    int idx = blockIdx.x * 256 + threadIdx.x;     // < 256*6912
    int m = idx / KDIM;
    int r = idx - m * KDIM;
    int kk = r / 768;
    int r2 = r - kk * 768;
    int s = r2 >> 8;
    int c = r2 & 255;
    float v = (m < M) ? w[((size_t)m * 256 + c) * 9 + kk] : 0.f;
    __nv_bfloat16 h = __float2bfloat16(v);
    A[idx] = (s == 2) ? __float2bfloat16(v - __bfloat162float(h)) : h;
}

// ---------------- NCHW fp32 -> NHWC hi/lo bf16 (+ optional fp32) ----------------
__global__ void tsplit_k(const float* __restrict__ in, __nv_bfloat16* __restrict__ hi,
                         __nv_bfloat16* __restrict__ lo, float* __restrict__ f32o) {
    __shared__ float t[32][33];
    int b = blockIdx.z, hw0 = blockIdx.x * 32, c0 = blockIdx.y * 32;
    int tx = threadIdx.x, ty = threadIdx.y;
    const float* ip = in + (size_t)b * 256 * 4096;
    for (int r = ty; r < 32; r += 8)
        t[r][tx] = ip[(size_t)(c0 + r) * 4096 + hw0 + tx];
    __syncthreads();
    for (int r = ty; r < 32; r += 8) {
        float v = t[tx][r];
        size_t idx = (size_t)b * 4096 * 256 + (size_t)(hw0 + r) * 256 + c0 + tx;
        __nv_bfloat16 h = __float2bfloat16(v);
        hi[idx] = h;
        lo[idx] = __float2bfloat16(v - __bfloat162float(h));
        if (f32o) f32o[idx] = v;
    }
}

// ---------------- mma.sync bf16 GEMM ----------------
// D[m][n] = sum_k A[m][k] * B[n][k]; CTA tile 128(M) x 128(N), K=6912.
// MODE 0: implicit conv, B gathered from NHWC bf16 hi/lo planes (zfill padding).
// MODE 1: B rows from col buffer [n][KSTORE] bf16 (deform).
template<int MODE>
__global__ __launch_bounds__(256, 2) void gemm_k(const __nv_bfloat16* __restrict__ A,
                                                 const __nv_bfloat16* __restrict__ Bhi,
                                                 const __nv_bfloat16* __restrict__ Blo,
                                                 float* __restrict__ out, int M, int bstride) {
    extern __shared__ char smx[];
    uint32_t smb = (smem_u32(smx) + 1023) & ~1023u;
    int tid = threadIdx.x;
    int lane = tid & 31;
    int w = tid >> 5;
    int wm = (w >> 2) * 64;       // 2 m-warp rows
    int wn = (w & 3) * 32;        // 4 n-warp cols
    int n0 = blockIdx.x * 128;
    int m0 = blockIdx.y * 128;
    int b = n0 >> 12, ij0 = n0 & 4095;
    int i0 = ij0 >> 6;

    auto load_chunk = [&](int t, uint32_t stg) {
        int kk = t / 12, rr = t - kk * 12, seg = rr >> 2, q = rr & 3;
        if (tid < 128) {
            int m = m0 + tid;
            const __nv_bfloat16* a0 = A + (size_t)m * KDIM + t * 64;
            int ss = (m < M) ? 16 : 0;
#pragma unroll
            for (int i = 0; i < 8; i++)
                cp16(stg + SWZ(tid * 128 + i * 16), a0 + i * 8, ss);
        } else {
            int r = tid - 128;
            const __nv_bfloat16* src;
            int ss = 16;
            if (MODE == 0) {
                int kd = kk / 3;
                int dy = kd - 1, dx = kk - kd * 3 - 1;
                int y = i0 + (r >> 6) + dy, x = (r & 63) + dx;
                bool v = ((unsigned)y < 64u) && ((unsigned)x < 64u);
                const __nv_bfloat16* plane = (seg == 1) ? Blo : Bhi;
                int yy = v ? y : 0, xx = v ? x : 0;
                src = plane + ((((size_t)b * 64 + yy) * 64 + xx) << 8) + q * 64;
                ss = v ? 16 : 0;
            } else {
                int srcseg = (seg == 2) ? 0 : seg;
                src = Bhi + (size_t)(n0 + r) * KSTORE + kk * 512 + srcseg * 256 + q * 64;
            }
#pragma unroll
            for (int i = 0; i < 8; i++)
                cp16(stg + 16384 + SWZ(r * 128 + i * 16), src + i * 8, ss);
        }
    };

    float acc[4][4][4];
#pragma unroll
    for (int im = 0; im < 4; im++)
#pragma unroll
        for (int jn = 0; jn < 4; jn++)
#pragma unroll
            for (int q = 0; q < 4; q++) acc[im][jn][q] = 0.f;

    load_chunk(0, smb);
    cp_commit();

    for (int t = 0; t < NCHUNK; t++) {
        if (t + 1 < NCHUNK) {
            load_chunk(t + 1, smb + ((t + 1) & 1) * 32768);
            cp_commit();
            cp_wait1();
        } else {
            cp_wait0();
        }
        __syncthreads();

        uint32_t aBase = smb + (t & 1) * 32768;
        uint32_t bBase = aBase + 16384;
#pragma unroll
        for (int s = 0; s < 4; s++) {
            uint32_t af[4][4];
#pragma unroll
            for (int im = 0; im < 4; im++) {
                int row = wm + im * 16 + (lane & 15);
                uint32_t off = row * 128 + s * 32 + (lane >> 4) * 16;
                ldm4(af[im], aBase + SWZ(off));
            }
            uint32_t bfr[4][2];
#pragma unroll
            for (int jp = 0; jp < 2; jp++) {
                int mi = lane >> 3;
                int row = wn + jp * 16 + (mi >> 1) * 8 + (lane & 7);
                uint32_t off = row * 128 + s * 32 + (mi & 1) * 16;
                uint32_t r4[4];
                ldm4(r4, bBase + SWZ(off));
                bfr[jp * 2][0] = r4[0]; bfr[jp * 2][1] = r4[1];
                bfr[jp * 2 + 1][0] = r4[2]; bfr[jp * 2 + 1][1] = r4[3];
            }
#pragma unroll
            for (int im = 0; im < 4; im++)
#pragma unroll
                for (int jn = 0; jn < 4; jn++)
                    mma16816(acc[im][jn], af[im], bfr[jn]);
        }
        __syncthreads();
    }

    // epilogue: D[m][n] fragments -> NCHW
    float* outb = out + (size_t)b * bstride + ij0;
#pragma unroll
    for (int im = 0; im < 4; im++) {
        int mrow = m0 + wm + im * 16 + (lane >> 2);
#pragma unroll
        for (int jn = 0; jn < 4; jn++) {
            int ncol = wn + jn * 8 + (lane & 3) * 2;
            if (mrow < M) {
                float2 v = make_float2(acc[im][jn][0], acc[im][jn][1]);
                *(float2*)(outb + (size_t)mrow * 4096 + ncol) = v;
            }
            if (mrow + 8 < M) {
                float2 v = make_float2(acc[im][jn][2], acc[im][jn][3]);
                *(float2*)(outb + (size_t)(mrow + 8) * 4096 + ncol) = v;
            }
        }
    }
}

// ---------------- GroupNorm (float4) ----------------
__global__ __launch_bounds__(256) void groupnorm_k(const float* __restrict__ in,
                                                   float* __restrict__ out,
                                                   const float* __restrict__ gamma,
                                                   const float* __restrict__ beta) {
    int bg = blockIdx.x;
    int b = bg >> 5, g = bg & 31;
    int tid = threadIdx.x;
    const float4* p = (const float4*)(in + ((size_t)b * 256 + g * 8) * 4096);
    float s = 0.f, s2 = 0.f;
    for (int i = tid; i < 8192; i += 256) {
        float4 v = p[i];
        s += v.x + v.y + v.z + v.w;
        s2 += v.x * v.x + v.y * v.y + v.z * v.z + v.w * v.w;
    }
    __shared__ float sA[256], sB[256];
    sA[tid] = s; sB[tid] = s2;
    __syncthreads();
    for (int st = 128; st > 0; st >>= 1) {
        if (tid < st) { sA[tid] += sA[tid + st]; sB[tid] += sB[tid + st]; }
        __syncthreads();
    }
    __shared__ float sm, sr;
    if (tid == 0) {
        float mean = sA[0] * (1.f / 32768.f);
        float var = sB[0] * (1.f / 32768.f) - mean * mean;
        sm = mean;
        sr = rsqrtf(var + 1e-5f);
    }
    __syncthreads();
    float mean = sm, rstd = sr;
    float4* o = (float4*)(out + ((size_t)b * 256 + g * 8) * 4096);
    for (int i = tid; i < 8192; i += 256) {
        int ch = g * 8 + (i >> 10);
        float ga = gamma[ch] * rstd, be = beta[ch];
        float4 v = p[i];
        v.x = (v.x - mean) * ga + be;
        v.y = (v.y - mean) * ga + be;
        v.z = (v.z - mean) * ga + be;
        v.w = (v.w - mean) * ga + be;
        o[i] = v;
    }
}

// ---------------- deformable bilinear gather -> bf16 hi/lo col ----------------
__global__ __launch_bounds__(256) void deform_col_k(const float* __restrict__ nhwc,
                                                    const float* __restrict__ off,
                                                    __nv_bfloat16* __restrict__ col) {
    int warp = (blockIdx.x * 256 + threadIdx.x) >> 5;
    int lane = threadIdx.x & 31;
    if (warp >= NG) return;
    int n = warp;
    int b = n >> 12, ij = n & 4095, i = ij >> 6, j = ij & 63;
    const float* offb = off + (size_t)b * 18 * 4096 + ij;
#pragma unroll
    for (int k = 0; k < 9; k++) {
        float dy = offb[(size_t)(2 * k) << 12];
        float dx = offb[(size_t)(2 * k + 1) << 12];
        float y = dy + (float)(i - 1 + k / 3);
        float x = dx + (float)(j - 1 + k % 3);
        float y0f = floorf(y), x0f = floorf(x);
        int y0 = (int)y0f, x0 = (int)x0f;
        float wy = y - y0f, wx = x - x0f;
        bool vy0 = (unsigned)y0 < 64u;
        bool vy1 = (unsigned)(y0 + 1) < 64u;
        bool vx0 = (unsigned)x0 < 64u;
        bool vx1 = (unsigned)(x0 + 1) < 64u;
        float w00 = (vy0 && vx0) ? (1.f - wy) * (1.f - wx) : 0.f;
        float w01 = (vy0 && vx1) ? (1.f - wy) * wx : 0.f;
        float w10 = (vy1 && vx0) ? wy * (1.f - wx) : 0.f;
        float w11 = (vy1 && vx1) ? wy * wx : 0.f;
        int cy0 = min(max(y0, 0), 63), cy1 = min(max(y0 + 1, 0), 63);
        int cx0 = min(max(x0, 0), 63), cx1 = min(max(x0 + 1, 0), 63);
        const float* p00 = nhwc + (((size_t)b * 64 + cy0) * 64 + cx0) * 256;
        const float* p01 = nhwc + (((size_t)b * 64 + cy0) * 64 + cx1) * 256;
        const float* p10 = nhwc + (((size_t)b * 64 + cy1) * 64 + cx0) * 256;
        const float* p11 = nhwc + (((size_t)b * 64 + cy1) * 64 + cx1) * 256;
        __nv_bfloat16* crow = col + (size_t)n * KSTORE + k * 512;
#pragma unroll
        for (int it = 0; it < 8; it++) {
            int c = lane + it * 32;
            float v = w00 * p00[c] + w01 * p01[c] + w10 * p10[c] + w11 * p11[c];
            __nv_bfloat16 h = __float2bfloat16(v);
            crow[c] = h;
            crow[256 + c] = __float2bfloat16(v - __bfloat162float(h));
        }
    }
}

// ---------------- rep-points epilogue ----------------
__global__ __launch_bounds__(256) void reppoints_k(const float* __restrict__ off1,
                                                   const float* __restrict__ off2,
                                                   float* __restrict__ out) {
    int idx = blockIdx.x * 256 + threadIdx.x;
    if (idx >= OFFN) return;
    int rem = idx % 73728;
    int ch = rem >> 12;
    int ij = rem & 4095;
    int i = ij >> 6, j = ij & 63;
    int k = ch >> 1;
    float init = (ch & 1) ? (float)(j + (k % 3) - 1) : (float)(i + (k / 3) - 1);
    float r1 = init + off1[idx];
    out[idx] = r1;
    out[OFFN + idx] = r1 + off2[idx];
}

// ---------------- host orchestration ----------------
extern "C" void kernel_launch(void* const* d_in, const int* in_sizes, int n_in,
                              void* d_out, int out_size) {
    const float* feature = (const float*)d_in[0];
    const float* loc_ws  = (const float*)d_in[1];
    const float* loc_g   = (const float*)d_in[2];
    const float* loc_b   = (const float*)d_in[3];
    const float* cls_ws  = (const float*)d_in[4];
    const float* cls_g   = (const float*)d_in[5];
    const float* cls_b   = (const float*)d_in[6];
    const float* pi_w    = (const float*)d_in[7];
    const float* pio_w   = (const float*)d_in[8];
    const float* prd_w   = (const float*)d_in[9];
    const float* pro_w   = (const float*)d_in[10];
    const float* cd_w    = (const float*)d_in[11];
    const float* co_w    = (const float*)d_in[12];
    float* out = (float*)d_out;

    static int attr_done = 0;
    if (!attr_done) {
        cudaFuncSetAttribute(gemm_k<0>, cudaFuncAttributeMaxDynamicSharedMemorySize, GEMM_SMEM);
        cudaFuncSetAttribute(gemm_k<1>, cudaFuncAttributeMaxDynamicSharedMemorySize, GEMM_SMEM);
        attr_done = 1;
    }

    __nv_bfloat16 *wa, *fhi, *flo, *thi, *tlo, *colb;
    float *nh1, *nh2, *bufA, *bufB, *off1, *off2;
    cudaGetSymbolAddress((void**)&wa,   g_wa);
    cudaGetSymbolAddress((void**)&fhi,  g_fhi);
    cudaGetSymbolAddress((void**)&flo,  g_flo);
    cudaGetSymbolAddress((void**)&thi,  g_thi);
    cudaGetSymbolAddress((void**)&tlo,  g_tlo);
    cudaGetSymbolAddress((void**)&colb, g_colb);
    cudaGetSymbolAddress((void**)&nh1,  g_nh1);
    cudaGetSymbolAddress((void**)&nh2,  g_nh2);
    cudaGetSymbolAddress((void**)&bufA, g_bufA);
    cudaGetSymbolAddress((void**)&bufB, g_bufB);
    cudaGetSymbolAddress((void**)&off1, g_off1);
    cudaGetSymbolAddress((void**)&off2, g_off2);

    dim3 tgrid(128, 8, 4), tblk(32, 8);
    dim3 g256(128, 2), g128(128, 1);

    // feature -> hi/lo NHWC (shared by both subnets)
    tsplit_k<<<tgrid, tblk>>>(feature, fhi, flo, nullptr);

    // loc subnet
    for (int l = 0; l < 3; l++) {
        wconv_k<<<6912, 256>>>(loc_ws + (size_t)l * WSZ, wa, 256);
        gemm_k<0><<<g256, 256, GEMM_SMEM>>>(wa, l == 0 ? fhi : thi, l == 0 ? flo : tlo,
                                            bufA, 256, 256 * 4096);
        groupnorm_k<<<128, 256>>>(bufA, bufB, loc_g + l * 256, loc_b + l * 256);
        tsplit_k<<<tgrid, tblk>>>(bufB, thi, tlo, l == 2 ? nh1 : nullptr);
    }
    // offset1 = conv(conv(loc, pi_w), pio_w)
    wconv_k<<<6912, 256>>>(pi_w, wa, 256);
    gemm_k<0><<<g256, 256, GEMM_SMEM>>>(wa, thi, tlo, bufA, 256, 256 * 4096);
    tsplit_k<<<tgrid, tblk>>>(bufA, thi, tlo, nullptr);
    wconv_k<<<6912, 256>>>(pio_w, wa, 18);
    gemm_k<0><<<g128, 256, GEMM_SMEM>>>(wa, thi, tlo, off1, 18, 18 * 4096);

    // cls subnet
    for (int l = 0; l < 3; l++) {
        wconv_k<<<6912, 256>>>(cls_ws + (size_t)l * WSZ, wa, 256);
        gemm_k<0><<<g256, 256, GEMM_SMEM>>>(wa, l == 0 ? fhi : thi, l == 0 ? flo : tlo,
                                            bufA, 256, 256 * 4096);
        groupnorm_k<<<128, 256>>>(bufA, bufB, cls_g + l * 256, cls_b + l * 256);
        tsplit_k<<<tgrid, tblk>>>(bufB, thi, tlo, l == 2 ? nh2 : nullptr);
    }

    // offset2 = conv(deform_conv(loc, offset1, prd_w), pro_w)
    deform_col_k<<<2048, 256>>>(nh1, off1, colb);
    wconv_k<<<6912, 256>>>(prd_w, wa, 256);
    gemm_k<1><<<g256, 256, GEMM_SMEM>>>(wa, colb, nullptr, bufA, 256, 256 * 4096);
    tsplit_k<<<tgrid, tblk>>>(bufA, thi, tlo, nullptr);
    wconv_k<<<6912, 256>>>(pro_w, wa, 18);
    gemm_k<0><<<g128, 256, GEMM_SMEM>>>(wa, thi, tlo, off2, 18, 18 * 4096);

    // classification = conv(deform_conv(cls, offset1, cd_w), co_w)
    deform_col_k<<<2048, 256>>>(nh2, off1, colb);
    wconv_k<<<6912, 256>>>(cd_w, wa, 256);
    gemm_k<1><<<g256, 256, GEMM_SMEM>>>(wa, colb, nullptr, bufA, 256, 256 * 4096);
    tsplit_k<<<tgrid, tblk>>>(bufA, thi, tlo, nullptr);
    wconv_k<<<6912, 256>>>(co_w, wa, 15);
    gemm_k<0><<<g128, 256, GEMM_SMEM>>>(wa, thi, tlo, out + 2 * OFFN, 15, 15 * 4096);

    // rp1 / rp2
    reppoints_k<<<(OFFN + 255) / 256, 256>>>(off1, off2, out);
}

// round 5
// speedup vs baseline: 3.3255x; 1.8461x over previous
#include <cuda_runtime.h>
#include <cuda_bf16.h>
#include <cstdint>
#include <math.h>

#define NG 16384
#define OFFN (18*16384)
#define KDIM 2304
#define NSTAGE 36            // 9 taps * 4 cgroups of 64
#define WSZ (256*256*9)
#define PL 589824            // 256*2304 per weight tensor
#define GEMM_SMEM 197632     // 2 * 96KB + 1KB align

// ---------------- scratch (device globals; no allocation) ----------------
__device__ __nv_bfloat16 g_wahi[(size_t)12*PL];
__device__ __nv_bfloat16 g_walo[(size_t)12*PL];
__device__ __nv_bfloat16 g_fhi[(size_t)NG*256];
__device__ __nv_bfloat16 g_flo[(size_t)NG*256];
__device__ __nv_bfloat16 g_thi[(size_t)NG*256];
__device__ __nv_bfloat16 g_tlo[(size_t)NG*256];
__device__ float g_nh1[(size_t)NG*256];
__device__ float g_nh2[(size_t)NG*256];
__device__ float g_bufA[(size_t)NG*256];
__device__ __nv_bfloat16 g_colh[(size_t)NG*KDIM];
__device__ __nv_bfloat16 g_coll[(size_t)NG*KDIM];
__device__ float g_off1[OFFN];
__device__ float g_off2[OFFN];
__device__ float g_ws[256];          // GN mean/rstd per (b,group)

// ---------------- PTX helpers ----------------
__device__ __forceinline__ uint32_t smem_u32(const void* p) {
    uint32_t a;
    asm("{ .reg .u64 t; cvta.to.shared.u64 t, %1; cvt.u32.u64 %0, t; }" : "=r"(a) : "l"(p));
    return a;
}
#define SWZ(o) ((o) ^ (((o) >> 3) & 0x70))

__device__ __forceinline__ void cp16(uint32_t dst, const void* src, int ss) {
    asm volatile("cp.async.cg.shared.global [%0], [%1], 16, %2;\n" :: "r"(dst), "l"(src), "r"(ss));
}
__device__ __forceinline__ void cp_commit() { asm volatile("cp.async.commit_group;\n" ::: "memory"); }
__device__ __forceinline__ void cp_wait0()  { asm volatile("cp.async.wait_group 0;\n" ::: "memory"); }
__device__ __forceinline__ void cp_wait1()  { asm volatile("cp.async.wait_group 1;\n" ::: "memory"); }

__device__ __forceinline__ void ldm4(uint32_t* r, uint32_t addr) {
    asm volatile("ldmatrix.sync.aligned.m8n8.x4.shared.b16 {%0,%1,%2,%3}, [%4];"
        : "=r"(r[0]), "=r"(r[1]), "=r"(r[2]), "=r"(r[3]) : "r"(addr));
}
__device__ __forceinline__ void mma16816(float* d, const uint32_t* a, const uint32_t* b) {
    asm volatile("mma.sync.aligned.m16n8k16.row.col.f32.bf16.bf16.f32 "
        "{%0,%1,%2,%3}, {%4,%5,%6,%7}, {%8,%9}, {%0,%1,%2,%3};"
        : "+f"(d[0]), "+f"(d[1]), "+f"(d[2]), "+f"(d[3])
        : "r"(a[0]), "r"(a[1]), "r"(a[2]), "r"(a[3]), "r"(b[0]), "r"(b[1]));
}

// ---------------- all-weights convert: fp32 [M][256][3][3] -> hi/lo [256][2304] ----
struct W12 { const float* p[12]; int m[12]; };
__global__ __launch_bounds__(256) void wconv_all_k(W12 w,
                                                   __nv_bfloat16* __restrict__ hi,
                                                   __nv_bfloat16* __restrict__ lo) {
    int idx = blockIdx.x * 256 + threadIdx.x;    // < 12*589824
    int t = idx / PL;
    int r = idx - t * PL;
    int m = r / KDIM;
    int k = r - m * KDIM;
    int kk = k >> 8, c = k & 255;
    float v = (m < w.m[t]) ? w.p[t][((size_t)m * 256 + c) * 9 + kk] : 0.f;
    __nv_bfloat16 h = __float2bfloat16(v);
    hi[idx] = h;
    lo[idx] = __float2bfloat16(v - __bfloat162float(h));
}

// ---------------- GN stats: one block per (b, group); ws[bg*2]={mean,rstd} ----
__global__ __launch_bounds__(256) void gnstat_k(const float* __restrict__ in,
                                                float* __restrict__ ws) {
    int bg = blockIdx.x;
    int b = bg >> 5, g = bg & 31;
    int tid = threadIdx.x;
    const float4* p = (const float4*)(in + ((size_t)b * 256 + g * 8) * 4096);
    float s = 0.f, s2 = 0.f;
    for (int i = tid; i < 8192; i += 256) {
        float4 v = p[i];
        s += v.x + v.y + v.z + v.w;
        s2 += v.x * v.x + v.y * v.y + v.z * v.z + v.w * v.w;
    }
    __shared__ float sA[256], sB[256];
    sA[tid] = s; sB[tid] = s2;
    __syncthreads();
    for (int st = 128; st > 0; st >>= 1) {
        if (tid < st) { sA[tid] += sA[tid + st]; sB[tid] += sB[tid + st]; }
        __syncthreads();
    }
    if (tid == 0) {
        float mean = sA[0] * (1.f / 32768.f);
        float var = sB[0] * (1.f / 32768.f) - mean * mean;
        ws[bg * 2] = mean;
        ws[bg * 2 + 1] = rsqrtf(var + 1e-5f);
    }
}

// ---------------- NCHW fp32 -> (optional GN affine) -> NHWC hi/lo bf16 (+fp32) ----
__global__ void tsplit_k(const float* __restrict__ in,
                         __nv_bfloat16* __restrict__ hi, __nv_bfloat16* __restrict__ lo,
                         float* __restrict__ f32o,
                         const float* __restrict__ ws,
                         const float* __restrict__ gamma, const float* __restrict__ beta) {
    __shared__ float t[32][33];
    int b = blockIdx.z, hw0 = blockIdx.x * 32, c0 = blockIdx.y * 32;
    int tx = threadIdx.x, ty = threadIdx.y;
    const float* ip = in + (size_t)b * 256 * 4096;
    for (int r = ty; r < 32; r += 8)
        t[r][tx] = ip[(size_t)(c0 + r) * 4096 + hw0 + tx];
    __syncthreads();
    int ch = c0 + tx;
    float sc = 1.f, sh = 0.f;
    if (ws) {
        int bg = b * 32 + (ch >> 3);
        float mean = ws[bg * 2], rstd = ws[bg * 2 + 1];
        sc = rstd * gamma[ch];
        sh = beta[ch] - mean * sc;
    }
    for (int r = ty; r < 32; r += 8) {
        float v = t[tx][r] * sc + sh;
        size_t idx = (size_t)b * 4096 * 256 + (size_t)(hw0 + r) * 256 + ch;
        if (hi) {
            __nv_bfloat16 h = __float2bfloat16(v);
            hi[idx] = h;
            lo[idx] = __float2bfloat16(v - __bfloat162float(h));
        }
        if (f32o) f32o[idx] = v;
    }
}

// ---------------- bf16 split-K GEMM: 128M x 256N tile, 512 threads ----------------
// D[m][n] = sum_k (AH+AL)[m][k]*(BH+BL)[n][k] via AH*BH + AH*BL + AL*BH.
// MODE 0: B gathered implicitly from NHWC hi/lo planes (zfill OOB taps).
// MODE 1: B from col planes [n][2304].
template<int MODE>
__global__ __launch_bounds__(512, 1) void gemm_k(const __nv_bfloat16* __restrict__ Ahi,
                                                 const __nv_bfloat16* __restrict__ Alo,
                                                 const __nv_bfloat16* __restrict__ Bhi,
                                                 const __nv_bfloat16* __restrict__ Blo,
                                                 float* __restrict__ out, int M, int bstride) {
    extern __shared__ char smx[];
    uint32_t smb = (smem_u32(smx) + 1023) & ~1023u;
    int tid = threadIdx.x;
    int lane = tid & 31;
    int wid = tid >> 5;
    int wm = (wid >> 3) * 64;
    int wn = (wid & 7) * 32;
    int n0 = blockIdx.x * 256;
    int m0 = blockIdx.y * 128;
    int b = n0 >> 12, ij0 = n0 & 4095;
    int i0 = ij0 >> 6;

    auto load_stage = [&](int t, uint32_t sb) {
        int kk = t >> 2, cg = t & 3;
        int koff = kk * 256 + cg * 64;
        int kd = kk / 3;
        int dy = kd - 1, dx = kk - kd * 3 - 1;
#pragma unroll
        for (int qi = 0; qi < 12; qi++) {
            int q = qi * 512 + tid;
            if (qi < 4) {
                int plane = (q >> 10) & 1;
                int qq = q & 1023;
                int row = qq >> 3, c16 = qq & 7;
                const __nv_bfloat16* src =
                    (plane ? Alo : Ahi) + (size_t)(m0 + row) * KDIM + koff + c16 * 8;
                cp16(sb + plane * 16384 + SWZ(row * 128 + c16 * 16), src, 16);
            } else {
                int qb = q - 2048;
                int plane = qb >> 11;
                int qq = qb & 2047;
                int row = qq >> 3, c16 = qq & 7;
                uint32_t dst = sb + 32768 + plane * 32768 + SWZ(row * 128 + c16 * 16);
                if (MODE == 0) {
                    int y = i0 + (row >> 6) + dy, x = (row & 63) + dx;
                    bool v = ((unsigned)y < 64u) && ((unsigned)x < 64u);
                    int yy = v ? y : 0, xx = v ? x : 0;
                    const __nv_bfloat16* src = (plane ? Blo : Bhi) +
                        ((((size_t)b * 64 + yy) * 64 + xx) << 8) + cg * 64 + c16 * 8;
                    cp16(dst, src, v ? 16 : 0);
                } else {
                    const __nv_bfloat16* src =
                        (plane ? Blo : Bhi) + (size_t)(n0 + row) * KDIM + koff + c16 * 8;
                    cp16(dst, src, 16);
                }
            }
        }
    };

    float acc[4][4][4];
#pragma unroll
    for (int im = 0; im < 4; im++)
#pragma unroll
        for (int jn = 0; jn < 4; jn++)
#pragma unroll
            for (int q = 0; q < 4; q++) acc[im][jn][q] = 0.f;

    load_stage(0, smb);
    cp_commit();

    // ldmatrix lane mappings (validated in R3)
    int arow_off = (lane & 15);
    int abyte = (lane >> 4) * 16;
    int mi = lane >> 3;
    int brow_off = (mi >> 1) * 8 + (lane & 7);
    int bbyte = (mi & 1) * 16;

    for (int t = 0; t < NSTAGE; t++) {
        if (t + 1 < NSTAGE) {
            load_stage(t + 1, smb + ((t + 1) & 1) * 98304);
            cp_commit();
            cp_wait1();
        } else {
            cp_wait0();
        }
        __syncthreads();

        uint32_t sb = smb + (t & 1) * 98304;
        uint32_t ahB = sb, alB = sb + 16384, bhB = sb + 32768, blB = sb + 65536;
#pragma unroll
        for (int s = 0; s < 4; s++) {
            uint32_t bh[4][2], bl[4][2];
#pragma unroll
            for (int jp = 0; jp < 2; jp++) {
                int rowb = wn + jp * 16 + brow_off;
                uint32_t off = SWZ(rowb * 128 + s * 32 + bbyte);
                uint32_t r4[4];
                ldm4(r4, bhB + off);
                bh[jp * 2][0] = r4[0]; bh[jp * 2][1] = r4[1];
                bh[jp * 2 + 1][0] = r4[2]; bh[jp * 2 + 1][1] = r4[3];
                ldm4(r4, blB + off);
                bl[jp * 2][0] = r4[0]; bl[jp * 2][1] = r4[1];
                bl[jp * 2 + 1][0] = r4[2]; bl[jp * 2 + 1][1] = r4[3];
            }
#pragma unroll
            for (int im = 0; im < 4; im++) {
                int rowa = wm + im * 16 + arow_off;
                uint32_t off = SWZ(rowa * 128 + s * 32 + abyte);
                uint32_t ah[4], al[4];
                ldm4(ah, ahB + off);
                ldm4(al, alB + off);
#pragma unroll
                for (int jn = 0; jn < 4; jn++) {
                    mma16816(acc[im][jn], ah, bh[jn]);
                    mma16816(acc[im][jn], ah, bl[jn]);
                    mma16816(acc[im][jn], al, bh[jn]);
                }
            }
        }
        __syncthreads();
    }

    // epilogue -> NCHW
    float* outb = out + (size_t)b * bstride + ij0;
#pragma unroll
    for (int im = 0; im < 4; im++) {
        int mrow = m0 + wm + im * 16 + (lane >> 2);
#pragma unroll
        for (int jn = 0; jn < 4; jn++) {
            int ncol = wn + jn * 8 + (lane & 3) * 2;
            if (mrow < M) {
                float2 v = make_float2(acc[im][jn][0], acc[im][jn][1]);
                *(float2*)(outb + (size_t)mrow * 4096 + ncol) = v;
            }
            if (mrow + 8 < M) {
                float2 v = make_float2(acc[im][jn][2], acc[im][jn][3]);
                *(float2*)(outb + (size_t)(mrow + 8) * 4096 + ncol) = v;
            }
        }
    }
}

// ---------------- deformable bilinear gather -> bf16 hi/lo col planes ----------------
__global__ __launch_bounds__(256) void deform_col_k(const float* __restrict__ nhwc,
                                                    const float* __restrict__ off,
                                                    __nv_bfloat16* __restrict__ colh,
                                                    __nv_bfloat16* __restrict__ coll) {
    int warp = (blockIdx.x * 256 + threadIdx.x) >> 5;
    int lane = threadIdx.x & 31;
    if (warp >= NG) return;
    int n = warp;
    int b = n >> 12, ij = n & 4095, i = ij >> 6, j = ij & 63;
    const float* offb = off + (size_t)b * 18 * 4096 + ij;
#pragma unroll
    for (int k = 0; k < 9; k++) {
        float dy = offb[(size_t)(2 * k) << 12];
        float dx = offb[(size_t)(2 * k + 1) << 12];
        float y = dy + (float)(i - 1 + k / 3);
        float x = dx + (float)(j - 1 + k % 3);
        float y0f = floorf(y), x0f = floorf(x);
        int y0 = (int)y0f, x0 = (int)x0f;
        float wy = y - y0f, wx = x - x0f;
        bool vy0 = (unsigned)y0 < 64u;
        bool vy1 = (unsigned)(y0 + 1) < 64u;
        bool vx0 = (unsigned)x0 < 64u;
        bool vx1 = (unsigned)(x0 + 1) < 64u;
        float w00 = (vy0 && vx0) ? (1.f - wy) * (1.f - wx) : 0.f;
        float w01 = (vy0 && vx1) ? (1.f - wy) * wx : 0.f;
        float w10 = (vy1 && vx0) ? wy * (1.f - wx) : 0.f;
        float w11 = (vy1 && vx1) ? wy * wx : 0.f;
        int cy0 = min(max(y0, 0), 63), cy1 = min(max(y0 + 1, 0), 63);
        int cx0 = min(max(x0, 0), 63), cx1 = min(max(x0 + 1, 0), 63);
        const float* p00 = nhwc + (((size_t)b * 64 + cy0) * 64 + cx0) * 256;
        const float* p01 = nhwc + (((size_t)b * 64 + cy0) * 64 + cx1) * 256;
        const float* p10 = nhwc + (((size_t)b * 64 + cy1) * 64 + cx0) * 256;
        const float* p11 = nhwc + (((size_t)b * 64 + cy1) * 64 + cx1) * 256;
        __nv_bfloat16* ch = colh + (size_t)n * KDIM + k * 256;
        __nv_bfloat16* cl = coll + (size_t)n * KDIM + k * 256;
#pragma unroll
        for (int it = 0; it < 8; it++) {
            int c = lane + it * 32;
            float v = w00 * p00[c] + w01 * p01[c] + w10 * p10[c] + w11 * p11[c];
            __nv_bfloat16 h = __float2bfloat16(v);
            ch[c] = h;
            cl[c] = __float2bfloat16(v - __bfloat162float(h));
        }
    }
}

// ---------------- rep-points epilogue ----------------
__global__ __launch_bounds__(256) void reppoints_k(const float* __restrict__ off1,
                                                   const float* __restrict__ off2,
                                                   float* __restrict__ out) {
    int idx = blockIdx.x * 256 + threadIdx.x;
    if (idx >= OFFN) return;
    int rem = idx % 73728;
    int ch = rem >> 12;
    int ij = rem & 4095;
    int i = ij >> 6, j = ij & 63;
    int k = ch >> 1;
    float init = (ch & 1) ? (float)(j + (k % 3) - 1) : (float)(i + (k / 3) - 1);
    float r1 = init + off1[idx];
    out[idx] = r1;
    out[OFFN + idx] = r1 + off2[idx];
}

// ---------------- host orchestration ----------------
extern "C" void kernel_launch(void* const* d_in, const int* in_sizes, int n_in,
                              void* d_out, int out_size) {
    const float* feature = (const float*)d_in[0];
    const float* loc_ws  = (const float*)d_in[1];
    const float* loc_g   = (const float*)d_in[2];
    const float* loc_b   = (const float*)d_in[3];
    const float* cls_ws  = (const float*)d_in[4];
    const float* cls_g   = (const float*)d_in[5];
    const float* cls_b   = (const float*)d_in[6];
    const float* pi_w    = (const float*)d_in[7];
    const float* pio_w   = (const float*)d_in[8];
    const float* prd_w   = (const float*)d_in[9];
    const float* pro_w   = (const float*)d_in[10];
    const float* cd_w    = (const float*)d_in[11];
    const float* co_w    = (const float*)d_in[12];
    float* out = (float*)d_out;

    static int attr_done = 0;
    if (!attr_done) {
        cudaFuncSetAttribute(gemm_k<0>, cudaFuncAttributeMaxDynamicSharedMemorySize, GEMM_SMEM);
        cudaFuncSetAttribute(gemm_k<1>, cudaFuncAttributeMaxDynamicSharedMemorySize, GEMM_SMEM);
        attr_done = 1;
    }

    __nv_bfloat16 *wahi, *walo, *fhi, *flo, *thi, *tlo, *colh, *coll;
    float *nh1, *nh2, *bufA, *off1, *off2, *ws;
    cudaGetSymbolAddress((void**)&wahi, g_wahi);
    cudaGetSymbolAddress((void**)&walo, g_walo);
    cudaGetSymbolAddress((void**)&fhi,  g_fhi);
    cudaGetSymbolAddress((void**)&flo,  g_flo);
    cudaGetSymbolAddress((void**)&thi,  g_thi);
    cudaGetSymbolAddress((void**)&tlo,  g_tlo);
    cudaGetSymbolAddress((void**)&colh, g_colh);
    cudaGetSymbolAddress((void**)&coll, g_coll);
    cudaGetSymbolAddress((void**)&nh1,  g_nh1);
    cudaGetSymbolAddress((void**)&nh2,  g_nh2);
    cudaGetSymbolAddress((void**)&bufA, g_bufA);
    cudaGetSymbolAddress((void**)&off1, g_off1);
    cudaGetSymbolAddress((void**)&off2, g_off2);
    cudaGetSymbolAddress((void**)&ws,   g_ws);

    // weight tensor order: loc0,loc1,loc2, cls0,cls1,cls2, pi,pio, prd,pro, cd,co
    W12 w12;
    w12.p[0] = loc_ws;           w12.m[0] = 256;
    w12.p[1] = loc_ws + WSZ;     w12.m[1] = 256;
    w12.p[2] = loc_ws + 2 * WSZ; w12.m[2] = 256;
    w12.p[3] = cls_ws;           w12.m[3] = 256;
    w12.p[4] = cls_ws + WSZ;     w12.m[4] = 256;
    w12.p[5] = cls_ws + 2 * WSZ; w12.m[5] = 256;
    w12.p[6] = pi_w;             w12.m[6] = 256;
    w12.p[7] = pio_w;            w12.m[7] = 18;
    w12.p[8] = prd_w;            w12.m[8] = 256;
    w12.p[9] = pro_w;            w12.m[9] = 18;
    w12.p[10] = cd_w;            w12.m[10] = 256;
    w12.p[11] = co_w;            w12.m[11] = 15;

    dim3 tgrid(128, 8, 4), tblk(32, 8);
    dim3 g256(64, 2), g128(64, 1);

    wconv_all_k<<<27648, 256>>>(w12, wahi, walo);
    tsplit_k<<<tgrid, tblk>>>(feature, fhi, flo, nullptr, nullptr, nullptr, nullptr);

    // loc subnet
    for (int l = 0; l < 3; l++) {
        gemm_k<0><<<g256, 512, GEMM_SMEM>>>(wahi + (size_t)l * PL, walo + (size_t)l * PL,
                                            l == 0 ? fhi : thi, l == 0 ? flo : tlo,
                                            bufA, 256, 256 * 4096);
        gnstat_k<<<128, 256>>>(bufA, ws);
        tsplit_k<<<tgrid, tblk>>>(bufA, thi, tlo, l == 2 ? nh1 : nullptr,
                                  ws, loc_g + l * 256, loc_b + l * 256);
    }
    // offset1 = conv(conv(loc, pi_w), pio_w)
    gemm_k<0><<<g256, 512, GEMM_SMEM>>>(wahi + 6 * (size_t)PL, walo + 6 * (size_t)PL,
                                        thi, tlo, bufA, 256, 256 * 4096);
    tsplit_k<<<tgrid, tblk>>>(bufA, thi, tlo, nullptr, nullptr, nullptr, nullptr);
    gemm_k<0><<<g128, 512, GEMM_SMEM>>>(wahi + 7 * (size_t)PL, walo + 7 * (size_t)PL,
                                        thi, tlo, off1, 18, 18 * 4096);

    // cls subnet
    for (int l = 0; l < 3; l++) {
        gemm_k<0><<<g256, 512, GEMM_SMEM>>>(wahi + (size_t)(3 + l) * PL, walo + (size_t)(3 + l) * PL,
                                            l == 0 ? fhi : thi, l == 0 ? flo : tlo,
                                            bufA, 256, 256 * 4096);
        gnstat_k<<<128, 256>>>(bufA, ws);
        tsplit_k<<<tgrid, tblk>>>(bufA, l == 2 ? nullptr : thi, l == 2 ? nullptr : tlo,
                                  l == 2 ? nh2 : nullptr,
                                  ws, cls_g + l * 256, cls_b + l * 256);
    }

    // offset2 = conv(deform_conv(loc, offset1, prd_w), pro_w)
    deform_col_k<<<2048, 256>>>(nh1, off1, colh, coll);
    gemm_k<1><<<g256, 512, GEMM_SMEM>>>(wahi + 8 * (size_t)PL, walo + 8 * (size_t)PL,
                                        colh, coll, bufA, 256, 256 * 4096);
    tsplit_k<<<tgrid, tblk>>>(bufA, thi, tlo, nullptr, nullptr, nullptr, nullptr);
    gemm_k<0><<<g128, 512, GEMM_SMEM>>>(wahi + 9 * (size_t)PL, walo + 9 * (size_t)PL,
                                        thi, tlo, off2, 18, 18 * 4096);

    // classification = conv(deform_conv(cls, offset1, cd_w), co_w)
    deform_col_k<<<2048, 256>>>(nh2, off1, colh, coll);
    gemm_k<1><<<g256, 512, GEMM_SMEM>>>(wahi + 10 * (size_t)PL, walo + 10 * (size_t)PL,
                                        colh, coll, bufA, 256, 256 * 4096);
    tsplit_k<<<tgrid, tblk>>>(bufA, thi, tlo, nullptr, nullptr, nullptr, nullptr);
    gemm_k<0><<<g128, 512, GEMM_SMEM>>>(wahi + 11 * (size_t)PL, walo + 11 * (size_t)PL,
                                        thi, tlo, out + 2 * OFFN, 15, 15 * 4096);

    // rp1 / rp2
    reppoints_k<<<(OFFN + 255) / 256, 256>>>(off1, off2, out);
}

// round 7
// speedup vs baseline: 3.8690x; 1.1634x over previous
#include <cuda_runtime.h>
#include <cuda_bf16.h>
#include <cstdint>
#include <math.h>

#define NG 16384
#define OFFN (18*16384)
#define KDIM 2304
#define WSZ (256*256*9)
#define PL 589824            // 256*2304 per weight tensor
#define COL_SMEM 197632      // deform col GEMM: 2*96KB + pad
#define SPL 25344            // slab plane bytes: 396 pix * 64B
#define BIG_SMEM 135168      // 2*2*8KB A + 2*2*SPL slabs + pad
#define SMALL_SMEM 110592    // 2*2*2KB A + slabs + pad

// ---------------- scratch (device globals; no allocation) ----------------
__device__ __nv_bfloat16 g_wahi[(size_t)12*PL];
__device__ __nv_bfloat16 g_walo[(size_t)12*PL];
__device__ __nv_bfloat16 g_fhi[(size_t)NG*256];
__device__ __nv_bfloat16 g_flo[(size_t)NG*256];
__device__ __nv_bfloat16 g_thi[(size_t)NG*256];
__device__ __nv_bfloat16 g_tlo[(size_t)NG*256];
__device__ float g_nh1[(size_t)NG*256];
__device__ float g_nh2[(size_t)NG*256];
__device__ float g_bufA[(size_t)NG*256];
__device__ __nv_bfloat16 g_colh[(size_t)NG*KDIM];
__device__ __nv_bfloat16 g_coll[(size_t)NG*KDIM];
__device__ float g_off1[OFFN];
__device__ float g_off2[OFFN];
__device__ float g_ws[256];

// ---------------- PTX helpers ----------------
__device__ __forceinline__ uint32_t smem_u32(const void* p) {
    uint32_t a;
    asm("{ .reg .u64 t; cvta.to.shared.u64 t, %1; cvt.u32.u64 %0, t; }" : "=r"(a) : "l"(p));
    return a;
}
#define SWZ(o)   ((o) ^ (((o) >> 3) & 0x70))
#define SWZ64(o) ((o) ^ (((o) >> 3) & 0x30))

__device__ __forceinline__ void cp16(uint32_t dst, const void* src, int ss) {
    asm volatile("cp.async.cg.shared.global [%0], [%1], 16, %2;\n" :: "r"(dst), "l"(src), "r"(ss));
}
__device__ __forceinline__ void cp_commit() { asm volatile("cp.async.commit_group;\n" ::: "memory"); }
__device__ __forceinline__ void cp_wait0()  { asm volatile("cp.async.wait_group 0;\n" ::: "memory"); }
__device__ __forceinline__ void cp_wait1()  { asm volatile("cp.async.wait_group 1;\n" ::: "memory"); }

__device__ __forceinline__ void ldm4(uint32_t* r, uint32_t addr) {
    asm volatile("ldmatrix.sync.aligned.m8n8.x4.shared.b16 {%0,%1,%2,%3}, [%4];"
        : "=r"(r[0]), "=r"(r[1]), "=r"(r[2]), "=r"(r[3]) : "r"(addr));
}
__device__ __forceinline__ void mma16816(float* d, const uint32_t* a, const uint32_t* b) {
    asm volatile("mma.sync.aligned.m16n8k16.row.col.f32.bf16.bf16.f32 "
        "{%0,%1,%2,%3}, {%4,%5,%6,%7}, {%8,%9}, {%0,%1,%2,%3};"
        : "+f"(d[0]), "+f"(d[1]), "+f"(d[2]), "+f"(d[3])
        : "r"(a[0]), "r"(a[1]), "r"(a[2]), "r"(a[3]), "r"(b[0]), "r"(b[1]));
}

// ---------------- all-weights convert ----------------
struct W12 { const float* p[12]; int m[12]; };
__global__ __launch_bounds__(256) void wconv_all_k(W12 w,
                                                   __nv_bfloat16* __restrict__ hi,
                                                   __nv_bfloat16* __restrict__ lo) {
    int idx = blockIdx.x * 256 + threadIdx.x;
    int t = idx / PL;
    int r = idx - t * PL;
    int m = r / KDIM;
    int k = r - m * KDIM;
    int kk = k >> 8, c = k & 255;
    float v = (m < w.m[t]) ? w.p[t][((size_t)m * 256 + c) * 9 + kk] : 0.f;
    __nv_bfloat16 h = __float2bfloat16(v);
    hi[idx] = h;
    lo[idx] = __float2bfloat16(v - __bfloat162float(h));
}

// ---------------- GN stats ----------------
__global__ __launch_bounds__(256) void gnstat_k(const float* __restrict__ in,
                                                float* __restrict__ ws) {
    int bg = blockIdx.x;
    int b = bg >> 5, g = bg & 31;
    int tid = threadIdx.x;
    const float4* p = (const float4*)(in + ((size_t)b * 256 + g * 8) * 4096);
    float s = 0.f, s2 = 0.f;
    for (int i = tid; i < 8192; i += 256) {
        float4 v = p[i];
        s += v.x + v.y + v.z + v.w;
        s2 += v.x * v.x + v.y * v.y + v.z * v.z + v.w * v.w;
    }
    __shared__ float sA[256], sB[256];
    sA[tid] = s; sB[tid] = s2;
    __syncthreads();
    for (int st = 128; st > 0; st >>= 1) {
        if (tid < st) { sA[tid] += sA[tid + st]; sB[tid] += sB[tid + st]; }
        __syncthreads();
    }
    if (tid == 0) {
        float mean = sA[0] * (1.f / 32768.f);
        float var = sB[0] * (1.f / 32768.f) - mean * mean;
        ws[bg * 2] = mean;
        ws[bg * 2 + 1] = rsqrtf(var + 1e-5f);
    }
}

// ---------------- NCHW fp32 -> (GN affine) -> NHWC hi/lo bf16 (+fp32) ----------------
__global__ void tsplit_k(const float* __restrict__ in,
                         __nv_bfloat16* __restrict__ hi, __nv_bfloat16* __restrict__ lo,
                         float* __restrict__ f32o,
                         const float* __restrict__ ws,
                         const float* __restrict__ gamma, const float* __restrict__ beta) {
    __shared__ float t[32][33];
    int b = blockIdx.z, hw0 = blockIdx.x * 32, c0 = blockIdx.y * 32;
    int tx = threadIdx.x, ty = threadIdx.y;
    const float* ip = in + (size_t)b * 256 * 4096;
    for (int r = ty; r < 32; r += 8)
        t[r][tx] = ip[(size_t)(c0 + r) * 4096 + hw0 + tx];
    __syncthreads();
    int ch = c0 + tx;
    float sc = 1.f, sh = 0.f;
    if (ws) {
        int bg = b * 32 + (ch >> 3);
        float mean = ws[bg * 2], rstd = ws[bg * 2 + 1];
        sc = rstd * gamma[ch];
        sh = beta[ch] - mean * sc;
    }
    for (int r = ty; r < 32; r += 8) {
        float v = t[tx][r] * sc + sh;
        size_t idx = (size_t)b * 4096 * 256 + (size_t)(hw0 + r) * 256 + ch;
        if (hi) {
            __nv_bfloat16 h = __float2bfloat16(v);
            hi[idx] = h;
            lo[idx] = __float2bfloat16(v - __bfloat162float(h));
        }
        if (f32o) f32o[idx] = v;
    }
}

// ---------------- slab-based implicit-conv GEMM ----------------
// D[m][n] = sum_k A[m][k]*B[n][k], split-K bf16 (AH*BH + AH*BL + AL*BH).
// B read implicitly from NHWC planes via a (6 x 66)-pixel x 32ch halo slab
// loaded once per channel group and shared by all 9 taps.
// 72 stages: t = cg*9 + tap, K=32 per stage.
template<int MROWS, int NTHREADS>
__global__ __launch_bounds__(NTHREADS, 1) void gemm_conv_k(
    const __nv_bfloat16* __restrict__ Ahi, const __nv_bfloat16* __restrict__ Alo,
    const __nv_bfloat16* __restrict__ Bhi, const __nv_bfloat16* __restrict__ Blo,
    float* __restrict__ out, int M, int bstride) {
    constexpr int MW = NTHREADS / 256;        // m-warp rows (2 or 1)
    constexpr int IM = MROWS / (MW * 16);     // 4 or 2
    constexpr int APL = MROWS * 64;           // A plane bytes / stage
    constexpr int AST = 2 * APL;              // A stage (hi+lo)
    constexpr int SST = 2 * SPL;              // slab (hi+lo)

    extern __shared__ char smx[];
    uint32_t smb = (smem_u32(smx) + 1023) & ~1023u;
    uint32_t aB = smb, sB = smb + 2 * AST;

    int tid = threadIdx.x;
    int lane = tid & 31;
    int wid = tid >> 5;
    int wm = (wid >> 3) * (IM * 16);
    int wn = (wid & 7) * 32;
    int n0 = blockIdx.x * 256;
    int m0 = blockIdx.y * MROWS;
    int b = n0 >> 12, ij0 = n0 & 4095;
    int i0 = ij0 >> 6;

    auto load_A = [&](int t, uint32_t dst) {
        int cg = t / 9, tap = t - cg * 9;
        int koff = tap * 256 + cg * 32;
#pragma unroll
        for (int idx = tid; idx < MROWS * 8; idx += NTHREADS) {
            int plane = idx >= MROWS * 4;
            int q = idx - plane * (MROWS * 4);
            int row = q >> 2, c16 = q & 3;
            const __nv_bfloat16* src =
                (plane ? Alo : Ahi) + (size_t)(m0 + row) * KDIM + koff + c16 * 8;
            cp16(dst + plane * APL + SWZ64(row * 64 + c16 * 16), src, 16);
        }
    };
    // slab: 396 pixels * 4 chunks = 1584 chunks per plane, 3168 total
    auto load_slab = [&](int cg, uint32_t dst) {
        for (int idx = tid; idx < 3168; idx += NTHREADS) {
            int plane = idx >= 1584;
            int q = idx - plane * 1584;
            int pix = q >> 2, c16 = q & 3;
            int sy = pix / 66, sx = pix - sy * 66;
            int y = i0 - 1 + sy, x = sx - 1;
            bool v = ((unsigned)y < 64u) && ((unsigned)x < 64u);
            int yy = v ? y : 0, xx = v ? x : 0;
            const __nv_bfloat16* src = (plane ? Blo : Bhi) +
                ((((size_t)b * 64 + yy) * 64 + xx) << 8) + cg * 32 + c16 * 8;
            cp16(dst + plane * SPL + SWZ64(pix * 64 + c16 * 16), src, v ? 16 : 0);
        }
    };

    float acc[IM][4][4];
#pragma unroll
    for (int im = 0; im < IM; im++)
#pragma unroll
        for (int jn = 0; jn < 4; jn++)
#pragma unroll
            for (int q = 0; q < 4; q++) acc[im][jn][q] = 0.f;

    int arow = lane & 15;
    int abyte = (lane >> 4) * 16;
    int mi = lane >> 3;
    int brow_off = (mi >> 1) * 8 + (lane & 7);
    int bbyte = (mi & 1) * 16;
    int b66[2];
#pragma unroll
    for (int jp = 0; jp < 2; jp++) {
        int rowb = wn + jp * 16 + brow_off;
        b66[jp] = (rowb >> 6) * 66 + (rowb & 63);
    }

    load_slab(0, sB);
    load_A(0, aB);
    cp_commit();

    for (int t = 0; t < 72; t++) {
        int cg = t / 9, tap = t - cg * 9;
        if (t + 1 < 72) {
            load_A(t + 1, aB + ((t + 1) & 1) * AST);
            if (tap == 4 && cg < 7) load_slab(cg + 1, sB + ((cg + 1) & 1) * SST);
            cp_commit();
            cp_wait1();
        } else {
            cp_wait0();
        }
        __syncthreads();

        uint32_t ab = aB + (t & 1) * AST;
        uint32_t sb = sB + (cg & 1) * SST;
        int kd = (tap * 11) >> 5;
        int tapoff = kd * 66 + (tap - kd * 3);
#pragma unroll
        for (int s = 0; s < 2; s++) {
            uint32_t bh[4][2], bl[4][2];
#pragma unroll
            for (int jp = 0; jp < 2; jp++) {
                int pix = b66[jp] + tapoff;
                uint32_t off = SWZ64(pix * 64 + s * 32 + bbyte);
                uint32_t r4[4];
                ldm4(r4, sb + off);
                bh[jp * 2][0] = r4[0]; bh[jp * 2][1] = r4[1];
                bh[jp * 2 + 1][0] = r4[2]; bh[jp * 2 + 1][1] = r4[3];
                ldm4(r4, sb + SPL + off);
                bl[jp * 2][0] = r4[0]; bl[jp * 2][1] = r4[1];
                bl[jp * 2 + 1][0] = r4[2]; bl[jp * 2 + 1][1] = r4[3];
            }
#pragma unroll
            for (int im = 0; im < IM; im++) {
                int rowa = wm + im * 16 + arow;
                uint32_t offa = SWZ64(rowa * 64 + s * 32 + abyte);
                uint32_t ah[4], al[4];
                ldm4(ah, ab + offa);
                ldm4(al, ab + APL + offa);
#pragma unroll
                for (int jn = 0; jn < 4; jn++) {
                    mma16816(acc[im][jn], ah, bh[jn]);
                    mma16816(acc[im][jn], ah, bl[jn]);
                    mma16816(acc[im][jn], al, bh[jn]);
                }
            }
        }
        __syncthreads();
    }

    float* outb = out + (size_t)b * bstride + ij0;
#pragma unroll
    for (int im = 0; im < IM; im++) {
        int mrow = m0 + wm + im * 16 + (lane >> 2);
#pragma unroll
        for (int jn = 0; jn < 4; jn++) {
            int ncol = wn + jn * 8 + (lane & 3) * 2;
            if (mrow < M) {
                float2 v = make_float2(acc[im][jn][0], acc[im][jn][1]);
                *(float2*)(outb + (size_t)mrow * 4096 + ncol) = v;
            }
            if (mrow + 8 < M) {
                float2 v = make_float2(acc[im][jn][2], acc[im][jn][3]);
                *(float2*)(outb + (size_t)(mrow + 8) * 4096 + ncol) = v;
            }
        }
    }
}

// ---------------- col-based GEMM for deform convs (proven R5 path) ----------------
__global__ __launch_bounds__(512, 1) void gemm_col_k(const __nv_bfloat16* __restrict__ Ahi,
                                                     const __nv_bfloat16* __restrict__ Alo,
                                                     const __nv_bfloat16* __restrict__ Bhi,
                                                     const __nv_bfloat16* __restrict__ Blo,
                                                     float* __restrict__ out, int M, int bstride) {
    extern __shared__ char smx[];
    uint32_t smb = (smem_u32(smx) + 1023) & ~1023u;
    int tid = threadIdx.x;
    int lane = tid & 31;
    int wid = tid >> 5;
    int wm = (wid >> 3) * 64;
    int wn = (wid & 7) * 32;
    int n0 = blockIdx.x * 256;
    int m0 = blockIdx.y * 128;
    int b = n0 >> 12, ij0 = n0 & 4095;

    auto load_stage = [&](int t, uint32_t sb) {
        int kk = t >> 2, cg = t & 3;
        int koff = kk * 256 + cg * 64;
#pragma unroll
        for (int qi = 0; qi < 12; qi++) {
            int q = qi * 512 + tid;
            if (qi < 4) {
                int plane = (q >> 10) & 1;
                int qq = q & 1023;
                int row = qq >> 3, c16 = qq & 7;
                const __nv_bfloat16* src =
                    (plane ? Alo : Ahi) + (size_t)(m0 + row) * KDIM + koff + c16 * 8;
                cp16(sb + plane * 16384 + SWZ(row * 128 + c16 * 16), src, 16);
            } else {
                int qb = q - 2048;
                int plane = qb >> 11;
                int qq = qb & 2047;
                int row = qq >> 3, c16 = qq & 7;
                const __nv_bfloat16* src =
                    (plane ? Blo : Bhi) + (size_t)(n0 + row) * KDIM + koff + c16 * 8;
                cp16(sb + 32768 + plane * 32768 + SWZ(row * 128 + c16 * 16), src, 16);
            }
        }
    };

    float acc[4][4][4];
#pragma unroll
    for (int im = 0; im < 4; im++)
#pragma unroll
        for (int jn = 0; jn < 4; jn++)
#pragma unroll
            for (int q = 0; q < 4; q++) acc[im][jn][q] = 0.f;

    load_stage(0, smb);
    cp_commit();

    int arow_off = (lane & 15);
    int abyte = (lane >> 4) * 16;
    int mi = lane >> 3;
    int brow_off = (mi >> 1) * 8 + (lane & 7);
    int bbyte = (mi & 1) * 16;

    for (int t = 0; t < 36; t++) {
        if (t + 1 < 36) {
            load_stage(t + 1, smb + ((t + 1) & 1) * 98304);
            cp_commit();
            cp_wait1();
        } else {
            cp_wait0();
        }
        __syncthreads();

        uint32_t sb = smb + (t & 1) * 98304;
        uint32_t ahB = sb, alB = sb + 16384, bhB = sb + 32768, blB = sb + 65536;
#pragma unroll
        for (int s = 0; s < 4; s++) {
            uint32_t bh[4][2], bl[4][2];
#pragma unroll
            for (int jp = 0; jp < 2; jp++) {
                int rowb = wn + jp * 16 + brow_off;
                uint32_t off = SWZ(rowb * 128 + s * 32 + bbyte);
                uint32_t r4[4];
                ldm4(r4, bhB + off);
                bh[jp * 2][0] = r4[0]; bh[jp * 2][1] = r4[1];
                bh[jp * 2 + 1][0] = r4[2]; bh[jp * 2 + 1][1] = r4[3];
                ldm4(r4, blB + off);
                bl[jp * 2][0] = r4[0]; bl[jp * 2][1] = r4[1];
                bl[jp * 2 + 1][0] = r4[2]; bl[jp * 2 + 1][1] = r4[3];
            }
#pragma unroll
            for (int im = 0; im < 4; im++) {
                int rowa = wm + im * 16 + arow_off;
                uint32_t off = SWZ(rowa * 128 + s * 32 + abyte);
                uint32_t ah[4], al[4];
                ldm4(ah, ahB + off);
                ldm4(al, alB + off);
#pragma unroll
                for (int jn = 0; jn < 4; jn++) {
                    mma16816(acc[im][jn], ah, bh[jn]);
                    mma16816(acc[im][jn], ah, bl[jn]);
                    mma16816(acc[im][jn], al, bh[jn]);
                }
            }
        }
        __syncthreads();
    }

    float* outb = out + (size_t)b * bstride + ij0;
#pragma unroll
    for (int im = 0; im < 4; im++) {
        int mrow = m0 + wm + im * 16 + (lane >> 2);
#pragma unroll
        for (int jn = 0; jn < 4; jn++) {
            int ncol = wn + jn * 8 + (lane & 3) * 2;
            if (mrow < M) {
                float2 v = make_float2(acc[im][jn][0], acc[im][jn][1]);
                *(float2*)(outb + (size_t)mrow * 4096 + ncol) = v;
            }
            if (mrow + 8 < M) {
                float2 v = make_float2(acc[im][jn][2], acc[im][jn][3]);
                *(float2*)(outb + (size_t)(mrow + 8) * 4096 + ncol) = v;
            }
        }
    }
}

// ---------------- deformable bilinear gather -> bf16 hi/lo col planes ----------------
__global__ __launch_bounds__(256) void deform_col_k(const float* __restrict__ nhwc,
                                                    const float* __restrict__ off,
                                                    __nv_bfloat16* __restrict__ colh,
                                                    __nv_bfloat16* __restrict__ coll) {
    int warp = (blockIdx.x * 256 + threadIdx.x) >> 5;
    int lane = threadIdx.x & 31;
    if (warp >= NG) return;
    int n = warp;
    int b = n >> 12, ij = n & 4095, i = ij >> 6, j = ij & 63;
    const float* offb = off + (size_t)b * 18 * 4096 + ij;
#pragma unroll
    for (int k = 0; k < 9; k++) {
        float dy = offb[(size_t)(2 * k) << 12];
        float dx = offb[(size_t)(2 * k + 1) << 12];
        float y = dy + (float)(i - 1 + k / 3);
        float x = dx + (float)(j - 1 + k % 3);
        float y0f = floorf(y), x0f = floorf(x);
        int y0 = (int)y0f, x0 = (int)x0f;
        float wy = y - y0f, wx = x - x0f;
        bool vy0 = (unsigned)y0 < 64u;
        bool vy1 = (unsigned)(y0 + 1) < 64u;
        bool vx0 = (unsigned)x0 < 64u;
        bool vx1 = (unsigned)(x0 + 1) < 64u;
        float w00 = (vy0 && vx0) ? (1.f - wy) * (1.f - wx) : 0.f;
        float w01 = (vy0 && vx1) ? (1.f - wy) * wx : 0.f;
        float w10 = (vy1 && vx0) ? wy * (1.f - wx) : 0.f;
        float w11 = (vy1 && vx1) ? wy * wx : 0.f;
        int cy0 = min(max(y0, 0), 63), cy1 = min(max(y0 + 1, 0), 63);
        int cx0 = min(max(x0, 0), 63), cx1 = min(max(x0 + 1, 0), 63);
        const float* p00 = nhwc + (((size_t)b * 64 + cy0) * 64 + cx0) * 256;
        const float* p01 = nhwc + (((size_t)b * 64 + cy0) * 64 + cx1) * 256;
        const float* p10 = nhwc + (((size_t)b * 64 + cy1) * 64 + cx0) * 256;
        const float* p11 = nhwc + (((size_t)b * 64 + cy1) * 64 + cx1) * 256;
        __nv_bfloat16* ch = colh + (size_t)n * KDIM + k * 256;
        __nv_bfloat16* cl = coll + (size_t)n * KDIM + k * 256;
#pragma unroll
        for (int it = 0; it < 8; it++) {
            int c = lane + it * 32;
            float v = w00 * p00[c] + w01 * p01[c] + w10 * p10[c] + w11 * p11[c];
            __nv_bfloat16 h = __float2bfloat16(v);
            ch[c] = h;
            cl[c] = __float2bfloat16(v - __bfloat162float(h));
        }
    }
}

// ---------------- rep-points epilogue ----------------
__global__ __launch_bounds__(256) void reppoints_k(const float* __restrict__ off1,
                                                   const float* __restrict__ off2,
                                                   float* __restrict__ out) {
    int idx = blockIdx.x * 256 + threadIdx.x;
    if (idx >= OFFN) return;
    int rem = idx % 73728;
    int ch = rem >> 12;
    int ij = rem & 4095;
    int i = ij >> 6, j = ij & 63;
    int k = ch >> 1;
    float init = (ch & 1) ? (float)(j + (k % 3) - 1) : (float)(i + (k / 3) - 1);
    float r1 = init + off1[idx];
    out[idx] = r1;
    out[OFFN + idx] = r1 + off2[idx];
}

// ---------------- host orchestration ----------------
extern "C" void kernel_launch(void* const* d_in, const int* in_sizes, int n_in,
                              void* d_out, int out_size) {
    const float* feature = (const float*)d_in[0];
    const float* loc_ws  = (const float*)d_in[1];
    const float* loc_g   = (const float*)d_in[2];
    const float* loc_b   = (const float*)d_in[3];
    const float* cls_ws  = (const float*)d_in[4];
    const float* cls_g   = (const float*)d_in[5];
    const float* cls_b   = (const float*)d_in[6];
    const float* pi_w    = (const float*)d_in[7];
    const float* pio_w   = (const float*)d_in[8];
    const float* prd_w   = (const float*)d_in[9];
    const float* pro_w   = (const float*)d_in[10];
    const float* cd_w    = (const float*)d_in[11];
    const float* co_w    = (const float*)d_in[12];
    float* out = (float*)d_out;

    static int attr_done = 0;
    if (!attr_done) {
        cudaFuncSetAttribute(gemm_conv_k<128, 512>, cudaFuncAttributeMaxDynamicSharedMemorySize, BIG_SMEM);
        cudaFuncSetAttribute(gemm_conv_k<32, 256>, cudaFuncAttributeMaxDynamicSharedMemorySize, SMALL_SMEM);
        cudaFuncSetAttribute(gemm_col_k, cudaFuncAttributeMaxDynamicSharedMemorySize, COL_SMEM);
        attr_done = 1;
    }

    __nv_bfloat16 *wahi, *walo, *fhi, *flo, *thi, *tlo, *colh, *coll;
    float *nh1, *nh2, *bufA, *off1, *off2, *ws;
    cudaGetSymbolAddress((void**)&wahi, g_wahi);
    cudaGetSymbolAddress((void**)&walo, g_walo);
    cudaGetSymbolAddress((void**)&fhi,  g_fhi);
    cudaGetSymbolAddress((void**)&flo,  g_flo);
    cudaGetSymbolAddress((void**)&thi,  g_thi);
    cudaGetSymbolAddress((void**)&tlo,  g_tlo);
    cudaGetSymbolAddress((void**)&colh, g_colh);
    cudaGetSymbolAddress((void**)&coll, g_coll);
    cudaGetSymbolAddress((void**)&nh1,  g_nh1);
    cudaGetSymbolAddress((void**)&nh2,  g_nh2);
    cudaGetSymbolAddress((void**)&bufA, g_bufA);
    cudaGetSymbolAddress((void**)&off1, g_off1);
    cudaGetSymbolAddress((void**)&off2, g_off2);
    cudaGetSymbolAddress((void**)&ws,   g_ws);

    W12 w12;
    w12.p[0] = loc_ws;           w12.m[0] = 256;
    w12.p[1] = loc_ws + WSZ;     w12.m[1] = 256;
    w12.p[2] = loc_ws + 2 * WSZ; w12.m[2] = 256;
    w12.p[3] = cls_ws;           w12.m[3] = 256;
    w12.p[4] = cls_ws + WSZ;     w12.m[4] = 256;
    w12.p[5] = cls_ws + 2 * WSZ; w12.m[5] = 256;
    w12.p[6] = pi_w;             w12.m[6] = 256;
    w12.p[7] = pio_w;            w12.m[7] = 18;
    w12.p[8] = prd_w;            w12.m[8] = 256;
    w12.p[9] = pro_w;            w12.m[9] = 18;
    w12.p[10] = cd_w;            w12.m[10] = 256;
    w12.p[11] = co_w;            w12.m[11] = 15;

    dim3 tgrid(128, 8, 4), tblk(32, 8);
    dim3 gBig(64, 2), gSmall(64, 1);

    wconv_all_k<<<27648, 256>>>(w12, wahi, walo);
    tsplit_k<<<tgrid, tblk>>>(feature, fhi, flo, nullptr, nullptr, nullptr, nullptr);

    // loc subnet
    for (int l = 0; l < 3; l++) {
        gemm_conv_k<128, 512><<<gBig, 512, BIG_SMEM>>>(
            wahi + (size_t)l * PL, walo + (size_t)l * PL,
            l == 0 ? fhi : thi, l == 0 ? flo : tlo, bufA, 256, 256 * 4096);
        gnstat_k<<<128, 256>>>(bufA, ws);
        tsplit_k<<<tgrid, tblk>>>(bufA, thi, tlo, l == 2 ? nh1 : nullptr,
                                  ws, loc_g + l * 256, loc_b + l * 256);
    }
    // offset1 = conv(conv(loc, pi_w), pio_w)
    gemm_conv_k<128, 512><<<gBig, 512, BIG_SMEM>>>(
        wahi + 6 * (size_t)PL, walo + 6 * (size_t)PL, thi, tlo, bufA, 256, 256 * 4096);
    tsplit_k<<<tgrid, tblk>>>(bufA, thi, tlo, nullptr, nullptr, nullptr, nullptr);
    gemm_conv_k<32, 256><<<gSmall, 256, SMALL_SMEM>>>(
        wahi + 7 * (size_t)PL, walo + 7 * (size_t)PL, thi, tlo, off1, 18, 18 * 4096);

    // cls subnet
    for (int l = 0; l < 3; l++) {
        gemm_conv_k<128, 512><<<gBig, 512, BIG_SMEM>>>(
            wahi + (size_t)(3 + l) * PL, walo + (size_t)(3 + l) * PL,
            l == 0 ? fhi : thi, l == 0 ? flo : tlo, bufA, 256, 256 * 4096);
        gnstat_k<<<128, 256>>>(bufA, ws);
        tsplit_k<<<tgrid, tblk>>>(bufA, l == 2 ? nullptr : thi, l == 2 ? nullptr : tlo,
                                  l == 2 ? nh2 : nullptr,
                                  ws, cls_g + l * 256, cls_b + l * 256);
    }

    // offset2 = conv(deform_conv(loc, offset1, prd_w), pro_w)
    deform_col_k<<<2048, 256>>>(nh1, off1, colh, coll);
    gemm_col_k<<<gBig, 512, COL_SMEM>>>(
        wahi + 8 * (size_t)PL, walo + 8 * (size_t)PL, colh, coll, bufA, 256, 256 * 4096);
    tsplit_k<<<tgrid, tblk>>>(bufA, thi, tlo, nullptr, nullptr, nullptr, nullptr);
    gemm_conv_k<32, 256><<<gSmall, 256, SMALL_SMEM>>>(
        wahi + 9 * (size_t)PL, walo + 9 * (size_t)PL, thi, tlo, off2, 18, 18 * 4096);

    // classification = conv(deform_conv(cls, offset1, cd_w), co_w)
    deform_col_k<<<2048, 256>>>(nh2, off1, colh, coll);
    gemm_col_k<<<gBig, 512, COL_SMEM>>>(
        wahi + 10 * (size_t)PL, walo + 10 * (size_t)PL, colh, coll, bufA, 256, 256 * 4096);
    tsplit_k<<<tgrid, tblk>>>(bufA, thi, tlo, nullptr, nullptr, nullptr, nullptr);
    gemm_conv_k<32, 256><<<gSmall, 256, SMALL_SMEM>>>(
        wahi + 11 * (size_t)PL, walo + 11 * (size_t)PL, thi, tlo, out + 2 * OFFN, 15, 15 * 4096);

    // rp1 / rp2
    reppoints_k<<<(OFFN + 255) / 256, 256>>>(off1, off2, out);
}

// round 8
// speedup vs baseline: 4.2812x; 1.1066x over previous
#include <cuda_runtime.h>
#include <cuda_bf16.h>
#include <cstdint>
#include <math.h>

#define NG 16384
#define OFFN (18*16384)
#define KDIM 2304
#define WSZ (256*256*9)
#define PL 589824            // 256*2304 per weight tensor
#define COL_SMEM 197632      // deform col GEMM: 2*96KB + pad
#define SPL 25344            // slab plane bytes: 396 pix * 64B
#define BIG_SMEM 135168
#define SMALL_SMEM 110592

// ---------------- scratch (device globals; no allocation) ----------------
__device__ __nv_bfloat16 g_wahi[(size_t)12*PL];
__device__ __nv_bfloat16 g_walo[(size_t)12*PL];
__device__ __nv_bfloat16 g_fhi[(size_t)NG*256];
__device__ __nv_bfloat16 g_flo[(size_t)NG*256];
// stream-1 (loc / offsets) scratch
__device__ __nv_bfloat16 g_t1hi[(size_t)NG*256];
__device__ __nv_bfloat16 g_t1lo[(size_t)NG*256];
__device__ float g_buf1[(size_t)NG*256];
__device__ float g_nh1[(size_t)NG*256];
__device__ __nv_bfloat16 g_col1h[(size_t)NG*KDIM];
__device__ __nv_bfloat16 g_col1l[(size_t)NG*KDIM];
__device__ float g_ws1[256];
// stream-2 (cls) scratch
__device__ __nv_bfloat16 g_t2hi[(size_t)NG*256];
__device__ __nv_bfloat16 g_t2lo[(size_t)NG*256];
__device__ float g_buf2[(size_t)NG*256];
__device__ float g_nh2[(size_t)NG*256];
__device__ __nv_bfloat16 g_col2h[(size_t)NG*KDIM];
__device__ __nv_bfloat16 g_col2l[(size_t)NG*KDIM];
__device__ float g_ws2[256];
__device__ float g_off1[OFFN];
__device__ float g_off2[OFFN];

// ---------------- PTX helpers ----------------
__device__ __forceinline__ uint32_t smem_u32(const void* p) {
    uint32_t a;
    asm("{ .reg .u64 t; cvta.to.shared.u64 t, %1; cvt.u32.u64 %0, t; }" : "=r"(a) : "l"(p));
    return a;
}
#define SWZ(o)   ((o) ^ (((o) >> 3) & 0x70))
#define SWZ64(o) ((o) ^ (((o) >> 3) & 0x30))

__device__ __forceinline__ void cp16(uint32_t dst, const void* src, int ss) {
    asm volatile("cp.async.cg.shared.global [%0], [%1], 16, %2;\n" :: "r"(dst), "l"(src), "r"(ss));
}
__device__ __forceinline__ void cp_commit() { asm volatile("cp.async.commit_group;\n" ::: "memory"); }
__device__ __forceinline__ void cp_wait0()  { asm volatile("cp.async.wait_group 0;\n" ::: "memory"); }
__device__ __forceinline__ void cp_wait1()  { asm volatile("cp.async.wait_group 1;\n" ::: "memory"); }

__device__ __forceinline__ void ldm4(uint32_t* r, uint32_t addr) {
    asm volatile("ldmatrix.sync.aligned.m8n8.x4.shared.b16 {%0,%1,%2,%3}, [%4];"
        : "=r"(r[0]), "=r"(r[1]), "=r"(r[2]), "=r"(r[3]) : "r"(addr));
}
__device__ __forceinline__ void mma16816(float* d, const uint32_t* a, const uint32_t* b) {
    asm volatile("mma.sync.aligned.m16n8k16.row.col.f32.bf16.bf16.f32 "
        "{%0,%1,%2,%3}, {%4,%5,%6,%7}, {%8,%9}, {%0,%1,%2,%3};"
        : "+f"(d[0]), "+f"(d[1]), "+f"(d[2]), "+f"(d[3])
        : "r"(a[0]), "r"(a[1]), "r"(a[2]), "r"(a[3]), "r"(b[0]), "r"(b[1]));
}

// ---------------- all-weights convert ----------------
struct W12 { const float* p[12]; int m[12]; };
__global__ __launch_bounds__(256) void wconv_all_k(W12 w,
                                                   __nv_bfloat16* __restrict__ hi,
                                                   __nv_bfloat16* __restrict__ lo) {
    int idx = blockIdx.x * 256 + threadIdx.x;
    int t = idx / PL;
    int r = idx - t * PL;
    int m = r / KDIM;
    int k = r - m * KDIM;
    int kk = k >> 8, c = k & 255;
    float v = (m < w.m[t]) ? w.p[t][((size_t)m * 256 + c) * 9 + kk] : 0.f;
    __nv_bfloat16 h = __float2bfloat16(v);
    hi[idx] = h;
    lo[idx] = __float2bfloat16(v - __bfloat162float(h));
}

// ---------------- GN stats ----------------
__global__ __launch_bounds__(256) void gnstat_k(const float* __restrict__ in,
                                                float* __restrict__ ws) {
    int bg = blockIdx.x;
    int b = bg >> 5, g = bg & 31;
    int tid = threadIdx.x;
    const float4* p = (const float4*)(in + ((size_t)b * 256 + g * 8) * 4096);
    float s = 0.f, s2 = 0.f;
    for (int i = tid; i < 8192; i += 256) {
        float4 v = p[i];
        s += v.x + v.y + v.z + v.w;
        s2 += v.x * v.x + v.y * v.y + v.z * v.z + v.w * v.w;
    }
    __shared__ float sA[256], sB[256];
    sA[tid] = s; sB[tid] = s2;
    __syncthreads();
    for (int st = 128; st > 0; st >>= 1) {
        if (tid < st) { sA[tid] += sA[tid + st]; sB[tid] += sB[tid + st]; }
        __syncthreads();
    }
    if (tid == 0) {
        float mean = sA[0] * (1.f / 32768.f);
        float var = sB[0] * (1.f / 32768.f) - mean * mean;
        ws[bg * 2] = mean;
        ws[bg * 2 + 1] = rsqrtf(var + 1e-5f);
    }
}

// ---------------- NCHW fp32 -> (GN affine) -> NHWC hi/lo bf16 (+fp32) ----------------
__global__ void tsplit_k(const float* __restrict__ in,
                         __nv_bfloat16* __restrict__ hi, __nv_bfloat16* __restrict__ lo,
                         float* __restrict__ f32o,
                         const float* __restrict__ ws,
                         const float* __restrict__ gamma, const float* __restrict__ beta) {
    __shared__ float t[32][33];
    int b = blockIdx.z, hw0 = blockIdx.x * 32, c0 = blockIdx.y * 32;
    int tx = threadIdx.x, ty = threadIdx.y;
    const float* ip = in + (size_t)b * 256 * 4096;
    for (int r = ty; r < 32; r += 8)
        t[r][tx] = ip[(size_t)(c0 + r) * 4096 + hw0 + tx];
    __syncthreads();
    int ch = c0 + tx;
    float sc = 1.f, sh = 0.f;
    if (ws) {
        int bg = b * 32 + (ch >> 3);
        float mean = ws[bg * 2], rstd = ws[bg * 2 + 1];
        sc = rstd * gamma[ch];
        sh = beta[ch] - mean * sc;
    }
    for (int r = ty; r < 32; r += 8) {
        float v = t[tx][r] * sc + sh;
        size_t idx = (size_t)b * 4096 * 256 + (size_t)(hw0 + r) * 256 + ch;
        if (hi) {
            __nv_bfloat16 h = __float2bfloat16(v);
            hi[idx] = h;
            lo[idx] = __float2bfloat16(v - __bfloat162float(h));
        }
        if (f32o) f32o[idx] = v;
    }
}

// ---------------- slab-based implicit-conv GEMM (R7, proven) ----------------
template<int MROWS, int NTHREADS>
__global__ __launch_bounds__(NTHREADS, 1) void gemm_conv_k(
    const __nv_bfloat16* __restrict__ Ahi, const __nv_bfloat16* __restrict__ Alo,
    const __nv_bfloat16* __restrict__ Bhi, const __nv_bfloat16* __restrict__ Blo,
    float* __restrict__ out, int M, int bstride) {
    constexpr int MW = NTHREADS / 256;
    constexpr int IM = MROWS / (MW * 16);
    constexpr int APL = MROWS * 64;
    constexpr int AST = 2 * APL;
    constexpr int SST = 2 * SPL;

    extern __shared__ char smx[];
    uint32_t smb = (smem_u32(smx) + 1023) & ~1023u;
    uint32_t aB = smb, sB = smb + 2 * AST;

    int tid = threadIdx.x;
    int lane = tid & 31;
    int wid = tid >> 5;
    int wm = (wid >> 3) * (IM * 16);
    int wn = (wid & 7) * 32;
    int n0 = blockIdx.x * 256;
    int m0 = blockIdx.y * MROWS;
    int b = n0 >> 12, ij0 = n0 & 4095;
    int i0 = ij0 >> 6;

    auto load_A = [&](int t, uint32_t dst) {
        int cg = t / 9, tap = t - cg * 9;
        int koff = tap * 256 + cg * 32;
#pragma unroll
        for (int idx = tid; idx < MROWS * 8; idx += NTHREADS) {
            int plane = idx >= MROWS * 4;
            int q = idx - plane * (MROWS * 4);
            int row = q >> 2, c16 = q & 3;
            const __nv_bfloat16* src =
                (plane ? Alo : Ahi) + (size_t)(m0 + row) * KDIM + koff + c16 * 8;
            cp16(dst + plane * APL + SWZ64(row * 64 + c16 * 16), src, 16);
        }
    };
    auto load_slab = [&](int cg, uint32_t dst) {
        for (int idx = tid; idx < 3168; idx += NTHREADS) {
            int plane = idx >= 1584;
            int q = idx - plane * 1584;
            int pix = q >> 2, c16 = q & 3;
            int sy = pix / 66, sx = pix - sy * 66;
            int y = i0 - 1 + sy, x = sx - 1;
            bool v = ((unsigned)y < 64u) && ((unsigned)x < 64u);
            int yy = v ? y : 0, xx = v ? x : 0;
            const __nv_bfloat16* src = (plane ? Blo : Bhi) +
                ((((size_t)b * 64 + yy) * 64 + xx) << 8) + cg * 32 + c16 * 8;
            cp16(dst + plane * SPL + SWZ64(pix * 64 + c16 * 16), src, v ? 16 : 0);
        }
    };

    float acc[IM][4][4];
#pragma unroll
    for (int im = 0; im < IM; im++)
#pragma unroll
        for (int jn = 0; jn < 4; jn++)
#pragma unroll
            for (int q = 0; q < 4; q++) acc[im][jn][q] = 0.f;

    int arow = lane & 15;
    int abyte = (lane >> 4) * 16;
    int mi = lane >> 3;
    int brow_off = (mi >> 1) * 8 + (lane & 7);
    int bbyte = (mi & 1) * 16;
    int b66[2];
#pragma unroll
    for (int jp = 0; jp < 2; jp++) {
        int rowb = wn + jp * 16 + brow_off;
        b66[jp] = (rowb >> 6) * 66 + (rowb & 63);
    }

    load_slab(0, sB);
    load_A(0, aB);
    cp_commit();

    for (int t = 0; t < 72; t++) {
        int cg = t / 9, tap = t - cg * 9;
        if (t + 1 < 72) {
            load_A(t + 1, aB + ((t + 1) & 1) * AST);
            if (tap == 4 && cg < 7) load_slab(cg + 1, sB + ((cg + 1) & 1) * SST);
            cp_commit();
            cp_wait1();
        } else {
            cp_wait0();
        }
        __syncthreads();

        uint32_t ab = aB + (t & 1) * AST;
        uint32_t sb = sB + (cg & 1) * SST;
        int kd = (tap * 11) >> 5;
        int tapoff = kd * 66 + (tap - kd * 3);
#pragma unroll
        for (int s = 0; s < 2; s++) {
            uint32_t bh[4][2], bl[4][2];
#pragma unroll
            for (int jp = 0; jp < 2; jp++) {
                int pix = b66[jp] + tapoff;
                uint32_t off = SWZ64(pix * 64 + s * 32 + bbyte);
                uint32_t r4[4];
                ldm4(r4, sb + off);
                bh[jp * 2][0] = r4[0]; bh[jp * 2][1] = r4[1];
                bh[jp * 2 + 1][0] = r4[2]; bh[jp * 2 + 1][1] = r4[3];
                ldm4(r4, sb + SPL + off);
                bl[jp * 2][0] = r4[0]; bl[jp * 2][1] = r4[1];
                bl[jp * 2 + 1][0] = r4[2]; bl[jp * 2 + 1][1] = r4[3];
            }
#pragma unroll
            for (int im = 0; im < IM; im++) {
                int rowa = wm + im * 16 + arow;
                uint32_t offa = SWZ64(rowa * 64 + s * 32 + abyte);
                uint32_t ah[4], al[4];
                ldm4(ah, ab + offa);
                ldm4(al, ab + APL + offa);
#pragma unroll
                for (int jn = 0; jn < 4; jn++) {
                    mma16816(acc[im][jn], ah, bh[jn]);
                    mma16816(acc[im][jn], ah, bl[jn]);
                    mma16816(acc[im][jn], al, bh[jn]);
                }
            }
        }
        __syncthreads();
    }

    float* outb = out + (size_t)b * bstride + ij0;
#pragma unroll
    for (int im = 0; im < IM; im++) {
        int mrow = m0 + wm + im * 16 + (lane >> 2);
#pragma unroll
        for (int jn = 0; jn < 4; jn++) {
            int ncol = wn + jn * 8 + (lane & 3) * 2;
            if (mrow < M) {
                float2 v = make_float2(acc[im][jn][0], acc[im][jn][1]);
                *(float2*)(outb + (size_t)mrow * 4096 + ncol) = v;
            }
            if (mrow + 8 < M) {
                float2 v = make_float2(acc[im][jn][2], acc[im][jn][3]);
                *(float2*)(outb + (size_t)(mrow + 8) * 4096 + ncol) = v;
            }
        }
    }
}

// ---------------- col-based GEMM for deform convs (R5, proven) ----------------
__global__ __launch_bounds__(512, 1) void gemm_col_k(const __nv_bfloat16* __restrict__ Ahi,
                                                     const __nv_bfloat16* __restrict__ Alo,
                                                     const __nv_bfloat16* __restrict__ Bhi,
                                                     const __nv_bfloat16* __restrict__ Blo,
                                                     float* __restrict__ out, int M, int bstride) {
    extern __shared__ char smx[];
    uint32_t smb = (smem_u32(smx) + 1023) & ~1023u;
    int tid = threadIdx.x;
    int lane = tid & 31;
    int wid = tid >> 5;
    int wm = (wid >> 3) * 64;
    int wn = (wid & 7) * 32;
    int n0 = blockIdx.x * 256;
    int m0 = blockIdx.y * 128;
    int b = n0 >> 12, ij0 = n0 & 4095;

    auto load_stage = [&](int t, uint32_t sb) {
        int kk = t >> 2, cg = t & 3;
        int koff = kk * 256 + cg * 64;
#pragma unroll
        for (int qi = 0; qi < 12; qi++) {
            int q = qi * 512 + tid;
            if (qi < 4) {
                int plane = (q >> 10) & 1;
                int qq = q & 1023;
                int row = qq >> 3, c16 = qq & 7;
                const __nv_bfloat16* src =
                    (plane ? Alo : Ahi) + (size_t)(m0 + row) * KDIM + koff + c16 * 8;
                cp16(sb + plane * 16384 + SWZ(row * 128 + c16 * 16), src, 16);
            } else {
                int qb = q - 2048;
                int plane = qb >> 11;
                int qq = qb & 2047;
                int row = qq >> 3, c16 = qq & 7;
                const __nv_bfloat16* src =
                    (plane ? Blo : Bhi) + (size_t)(n0 + row) * KDIM + koff + c16 * 8;
                cp16(sb + 32768 + plane * 32768 + SWZ(row * 128 + c16 * 16), src, 16);
            }
        }
    };

    float acc[4][4][4];
#pragma unroll
    for (int im = 0; im < 4; im++)
#pragma unroll
        for (int jn = 0; jn < 4; jn++)
#pragma unroll
            for (int q = 0; q < 4; q++) acc[im][jn][q] = 0.f;

    load_stage(0, smb);
    cp_commit();

    int arow_off = (lane & 15);
    int abyte = (lane >> 4) * 16;
    int mi = lane >> 3;
    int brow_off = (mi >> 1) * 8 + (lane & 7);
    int bbyte = (mi & 1) * 16;

    for (int t = 0; t < 36; t++) {
        if (t + 1 < 36) {
            load_stage(t + 1, smb + ((t + 1) & 1) * 98304);
            cp_commit();
            cp_wait1();
        } else {
            cp_wait0();
        }
        __syncthreads();

        uint32_t sb = smb + (t & 1) * 98304;
        uint32_t ahB = sb, alB = sb + 16384, bhB = sb + 32768, blB = sb + 65536;
#pragma unroll
        for (int s = 0; s < 4; s++) {
            uint32_t bh[4][2], bl[4][2];
#pragma unroll
            for (int jp = 0; jp < 2; jp++) {
                int rowb = wn + jp * 16 + brow_off;
                uint32_t off = SWZ(rowb * 128 + s * 32 + bbyte);
                uint32_t r4[4];
                ldm4(r4, bhB + off);
                bh[jp * 2][0] = r4[0]; bh[jp * 2][1] = r4[1];
                bh[jp * 2 + 1][0] = r4[2]; bh[jp * 2 + 1][1] = r4[3];
                ldm4(r4, blB + off);
                bl[jp * 2][0] = r4[0]; bl[jp * 2][1] = r4[1];
                bl[jp * 2 + 1][0] = r4[2]; bl[jp * 2 + 1][1] = r4[3];
            }
#pragma unroll
            for (int im = 0; im < 4; im++) {
                int rowa = wm + im * 16 + arow_off;
                uint32_t off = SWZ(rowa * 128 + s * 32 + abyte);
                uint32_t ah[4], al[4];
                ldm4(ah, ahB + off);
                ldm4(al, alB + off);
#pragma unroll
                for (int jn = 0; jn < 4; jn++) {
                    mma16816(acc[im][jn], ah, bh[jn]);
                    mma16816(acc[im][jn], ah, bl[jn]);
                    mma16816(acc[im][jn], al, bh[jn]);
                }
            }
        }
        __syncthreads();
    }

    float* outb = out + (size_t)b * bstride + ij0;
#pragma unroll
    for (int im = 0; im < 4; im++) {
        int mrow = m0 + wm + im * 16 + (lane >> 2);
#pragma unroll
        for (int jn = 0; jn < 4; jn++) {
            int ncol = wn + jn * 8 + (lane & 3) * 2;
            if (mrow < M) {
                float2 v = make_float2(acc[im][jn][0], acc[im][jn][1]);
                *(float2*)(outb + (size_t)mrow * 4096 + ncol) = v;
            }
            if (mrow + 8 < M) {
                float2 v = make_float2(acc[im][jn][2], acc[im][jn][3]);
                *(float2*)(outb + (size_t)(mrow + 8) * 4096 + ncol) = v;
            }
        }
    }
}

// ---------------- deformable bilinear gather -> bf16 hi/lo col planes ----------------
__global__ __launch_bounds__(256) void deform_col_k(const float* __restrict__ nhwc,
                                                    const float* __restrict__ off,
                                                    __nv_bfloat16* __restrict__ colh,
                                                    __nv_bfloat16* __restrict__ coll) {
    int warp = (blockIdx.x * 256 + threadIdx.x) >> 5;
    int lane = threadIdx.x & 31;
    if (warp >= NG) return;
    int n = warp;
    int b = n >> 12, ij = n & 4095, i = ij >> 6, j = ij & 63;
    const float* offb = off + (size_t)b * 18 * 4096 + ij;
#pragma unroll
    for (int k = 0; k < 9; k++) {
        float dy = offb[(size_t)(2 * k) << 12];
        float dx = offb[(size_t)(2 * k + 1) << 12];
        float y = dy + (float)(i - 1 + k / 3);
        float x = dx + (float)(j - 1 + k % 3);
        float y0f = floorf(y), x0f = floorf(x);
        int y0 = (int)y0f, x0 = (int)x0f;
        float wy = y - y0f, wx = x - x0f;
        bool vy0 = (unsigned)y0 < 64u;
        bool vy1 = (unsigned)(y0 + 1) < 64u;
        bool vx0 = (unsigned)x0 < 64u;
        bool vx1 = (unsigned)(x0 + 1) < 64u;
        float w00 = (vy0 && vx0) ? (1.f - wy) * (1.f - wx) : 0.f;
        float w01 = (vy0 && vx1) ? (1.f - wy) * wx : 0.f;
        float w10 = (vy1 && vx0) ? wy * (1.f - wx) : 0.f;
        float w11 = (vy1 && vx1) ? wy * wx : 0.f;
        int cy0 = min(max(y0, 0), 63), cy1 = min(max(y0 + 1, 0), 63);
        int cx0 = min(max(x0, 0), 63), cx1 = min(max(x0 + 1, 0), 63);
        const float* p00 = nhwc + (((size_t)b * 64 + cy0) * 64 + cx0) * 256;
        const float* p01 = nhwc + (((size_t)b * 64 + cy0) * 64 + cx1) * 256;
        const float* p10 = nhwc + (((size_t)b * 64 + cy1) * 64 + cx0) * 256;
        const float* p11 = nhwc + (((size_t)b * 64 + cy1) * 64 + cx1) * 256;
        __nv_bfloat16* ch = colh + (size_t)n * KDIM + k * 256;
        __nv_bfloat16* cl = coll + (size_t)n * KDIM + k * 256;
#pragma unroll
        for (int it = 0; it < 8; it++) {
            int c = lane + it * 32;
            float v = w00 * p00[c] + w01 * p01[c] + w10 * p10[c] + w11 * p11[c];
            __nv_bfloat16 h = __float2bfloat16(v);
            ch[c] = h;
            cl[c] = __float2bfloat16(v - __bfloat162float(h));
        }
    }
}

// ---------------- rep-points epilogue ----------------
__global__ __launch_bounds__(256) void reppoints_k(const float* __restrict__ off1,
                                                   const float* __restrict__ off2,
                                                   float* __restrict__ out) {
    int idx = blockIdx.x * 256 + threadIdx.x;
    if (idx >= OFFN) return;
    int rem = idx % 73728;
    int ch = rem >> 12;
    int ij = rem & 4095;
    int i = ij >> 6, j = ij & 63;
    int k = ch >> 1;
    float init = (ch & 1) ? (float)(j + (k % 3) - 1) : (float)(i + (k / 3) - 1);
    float r1 = init + off1[idx];
    out[idx] = r1;
    out[OFFN + idx] = r1 + off2[idx];
}

// ---------------- host orchestration (2-stream overlap) ----------------
extern "C" void kernel_launch(void* const* d_in, const int* in_sizes, int n_in,
                              void* d_out, int out_size) {
    const float* feature = (const float*)d_in[0];
    const float* loc_ws  = (const float*)d_in[1];
    const float* loc_g   = (const float*)d_in[2];
    const float* loc_b   = (const float*)d_in[3];
    const float* cls_ws  = (const float*)d_in[4];
    const float* cls_g   = (const float*)d_in[5];
    const float* cls_b   = (const float*)d_in[6];
    const float* pi_w    = (const float*)d_in[7];
    const float* pio_w   = (const float*)d_in[8];
    const float* prd_w   = (const float*)d_in[9];
    const float* pro_w   = (const float*)d_in[10];
    const float* cd_w    = (const float*)d_in[11];
    const float* co_w    = (const float*)d_in[12];
    float* out = (float*)d_out;

    static int init_done = 0;
    static cudaStream_t s1, s2;
    static cudaEvent_t evRoot, evW, evF, evOff1, evE1, evE2;
    if (!init_done) {
        cudaFuncSetAttribute(gemm_conv_k<128, 512>, cudaFuncAttributeMaxDynamicSharedMemorySize, BIG_SMEM);
        cudaFuncSetAttribute(gemm_conv_k<32, 256>, cudaFuncAttributeMaxDynamicSharedMemorySize, SMALL_SMEM);
        cudaFuncSetAttribute(gemm_col_k, cudaFuncAttributeMaxDynamicSharedMemorySize, COL_SMEM);
        cudaStreamCreateWithFlags(&s1, cudaStreamNonBlocking);
        cudaStreamCreateWithFlags(&s2, cudaStreamNonBlocking);
        cudaEventCreateWithFlags(&evRoot, cudaEventDisableTiming);
        cudaEventCreateWithFlags(&evW, cudaEventDisableTiming);
        cudaEventCreateWithFlags(&evF, cudaEventDisableTiming);
        cudaEventCreateWithFlags(&evOff1, cudaEventDisableTiming);
        cudaEventCreateWithFlags(&evE1, cudaEventDisableTiming);
        cudaEventCreateWithFlags(&evE2, cudaEventDisableTiming);
        init_done = 1;
    }

    __nv_bfloat16 *wahi, *walo, *fhi, *flo;
    __nv_bfloat16 *t1hi, *t1lo, *col1h, *col1l, *t2hi, *t2lo, *col2h, *col2l;
    float *buf1, *buf2, *nh1, *nh2, *off1, *off2, *ws1, *ws2;
    cudaGetSymbolAddress((void**)&wahi,  g_wahi);
    cudaGetSymbolAddress((void**)&walo,  g_walo);
    cudaGetSymbolAddress((void**)&fhi,   g_fhi);
    cudaGetSymbolAddress((void**)&flo,   g_flo);
    cudaGetSymbolAddress((void**)&t1hi,  g_t1hi);
    cudaGetSymbolAddress((void**)&t1lo,  g_t1lo);
    cudaGetSymbolAddress((void**)&col1h, g_col1h);
    cudaGetSymbolAddress((void**)&col1l, g_col1l);
    cudaGetSymbolAddress((void**)&t2hi,  g_t2hi);
    cudaGetSymbolAddress((void**)&t2lo,  g_t2lo);
    cudaGetSymbolAddress((void**)&col2h, g_col2h);
    cudaGetSymbolAddress((void**)&col2l, g_col2l);
    cudaGetSymbolAddress((void**)&buf1,  g_buf1);
    cudaGetSymbolAddress((void**)&buf2,  g_buf2);
    cudaGetSymbolAddress((void**)&nh1,   g_nh1);
    cudaGetSymbolAddress((void**)&nh2,   g_nh2);
    cudaGetSymbolAddress((void**)&off1,  g_off1);
    cudaGetSymbolAddress((void**)&off2,  g_off2);
    cudaGetSymbolAddress((void**)&ws1,   g_ws1);
    cudaGetSymbolAddress((void**)&ws2,   g_ws2);

    W12 w12;
    w12.p[0] = loc_ws;           w12.m[0] = 256;
    w12.p[1] = loc_ws + WSZ;     w12.m[1] = 256;
    w12.p[2] = loc_ws + 2 * WSZ; w12.m[2] = 256;
    w12.p[3] = cls_ws;           w12.m[3] = 256;
    w12.p[4] = cls_ws + WSZ;     w12.m[4] = 256;
    w12.p[5] = cls_ws + 2 * WSZ; w12.m[5] = 256;
    w12.p[6] = pi_w;             w12.m[6] = 256;
    w12.p[7] = pio_w;            w12.m[7] = 18;
    w12.p[8] = prd_w;            w12.m[8] = 256;
    w12.p[9] = pro_w;            w12.m[9] = 18;
    w12.p[10] = cd_w;            w12.m[10] = 256;
    w12.p[11] = co_w;            w12.m[11] = 15;

    dim3 tgrid(128, 8, 4), tblk(32, 8);
    dim3 gBig(64, 2), gSmall(64, 1);

    // fork from the capturing (default) stream
    cudaEventRecord(evRoot, 0);
    cudaStreamWaitEvent(s1, evRoot, 0);
    cudaStreamWaitEvent(s2, evRoot, 0);

    // s1: weights; s2: feature split — then cross-sync
    wconv_all_k<<<27648, 256, 0, s1>>>(w12, wahi, walo);
    cudaEventRecord(evW, s1);
    tsplit_k<<<tgrid, tblk, 0, s2>>>(feature, fhi, flo, nullptr, nullptr, nullptr, nullptr);
    cudaEventRecord(evF, s2);
    cudaStreamWaitEvent(s1, evF, 0);
    cudaStreamWaitEvent(s2, evW, 0);

    // ---- s1: loc subnet -> offset1 -> offset2 branch -> reppoints ----
    for (int l = 0; l < 3; l++) {
        gemm_conv_k<128, 512><<<gBig, 512, BIG_SMEM, s1>>>(
            wahi + (size_t)l * PL, walo + (size_t)l * PL,
            l == 0 ? fhi : t1hi, l == 0 ? flo : t1lo, buf1, 256, 256 * 4096);
        gnstat_k<<<128, 256, 0, s1>>>(buf1, ws1);
        tsplit_k<<<tgrid, tblk, 0, s1>>>(buf1, t1hi, t1lo, l == 2 ? nh1 : nullptr,
                                         ws1, loc_g + l * 256, loc_b + l * 256);
    }
    gemm_conv_k<128, 512><<<gBig, 512, BIG_SMEM, s1>>>(
        wahi + 6 * (size_t)PL, walo + 6 * (size_t)PL, t1hi, t1lo, buf1, 256, 256 * 4096);
    tsplit_k<<<tgrid, tblk, 0, s1>>>(buf1, t1hi, t1lo, nullptr, nullptr, nullptr, nullptr);
    gemm_conv_k<32, 256><<<gSmall, 256, SMALL_SMEM, s1>>>(
        wahi + 7 * (size_t)PL, walo + 7 * (size_t)PL, t1hi, t1lo, off1, 18, 18 * 4096);
    cudaEventRecord(evOff1, s1);

    deform_col_k<<<2048, 256, 0, s1>>>(nh1, off1, col1h, col1l);
    gemm_col_k<<<gBig, 512, COL_SMEM, s1>>>(
        wahi + 8 * (size_t)PL, walo + 8 * (size_t)PL, col1h, col1l, buf1, 256, 256 * 4096);
    tsplit_k<<<tgrid, tblk, 0, s1>>>(buf1, t1hi, t1lo, nullptr, nullptr, nullptr, nullptr);
    gemm_conv_k<32, 256><<<gSmall, 256, SMALL_SMEM, s1>>>(
        wahi + 9 * (size_t)PL, walo + 9 * (size_t)PL, t1hi, t1lo, off2, 18, 18 * 4096);
    reppoints_k<<<(OFFN + 255) / 256, 256, 0, s1>>>(off1, off2, out);
    cudaEventRecord(evE1, s1);

    // ---- s2: cls subnet -> classification branch ----
    for (int l = 0; l < 3; l++) {
        gemm_conv_k<128, 512><<<gBig, 512, BIG_SMEM, s2>>>(
            wahi + (size_t)(3 + l) * PL, walo + (size_t)(3 + l) * PL,
            l == 0 ? fhi : t2hi, l == 0 ? flo : t2lo, buf2, 256, 256 * 4096);
        gnstat_k<<<128, 256, 0, s2>>>(buf2, ws2);
        tsplit_k<<<tgrid, tblk, 0, s2>>>(buf2, l == 2 ? nullptr : t2hi, l == 2 ? nullptr : t2lo,
                                         l == 2 ? nh2 : nullptr,
                                         ws2, cls_g + l * 256, cls_b + l * 256);
    }
    cudaStreamWaitEvent(s2, evOff1, 0);
    deform_col_k<<<2048, 256, 0, s2>>>(nh2, off1, col2h, col2l);
    gemm_col_k<<<gBig, 512, COL_SMEM, s2>>>(
        wahi + 10 * (size_t)PL, walo + 10 * (size_t)PL, col2h, col2l, buf2, 256, 256 * 4096);
    tsplit_k<<<tgrid, tblk, 0, s2>>>(buf2, t2hi, t2lo, nullptr, nullptr, nullptr, nullptr);
    gemm_conv_k<32, 256><<<gSmall, 256, SMALL_SMEM, s2>>>(
        wahi + 11 * (size_t)PL, walo + 11 * (size_t)PL, t2hi, t2lo, out + 2 * OFFN, 15, 15 * 4096);
    cudaEventRecord(evE2, s2);

    // join back into the capturing stream
    cudaStreamWaitEvent(0, evE1, 0);
    cudaStreamWaitEvent(0, evE2, 0);
}

// round 9
// speedup vs baseline: 4.3098x; 1.0067x over previous
#include <cuda_runtime.h>
#include <cuda_bf16.h>
#include <cstdint>
#include <math.h>

#define NG 16384
#define OFFN (18*16384)
#define KDIM 2304
#define WSZ (256*256*9)
#define PL 589824            // 256*2304 per weight tensor
#define COL_SMEM 197632      // deform col GEMM: 2*96KB + pad
#define SPL 25344            // slab plane bytes: 396 pix * 64B
#define BIG_SMEM 135168
#define SMALL_SMEM 110592

// ---------------- scratch (device globals; no allocation) ----------------
__device__ __nv_bfloat16 g_wahi[(size_t)12*PL];
__device__ __nv_bfloat16 g_walo[(size_t)12*PL];
__device__ __nv_bfloat16 g_fhi[(size_t)NG*256];
__device__ __nv_bfloat16 g_flo[(size_t)NG*256];
// stream-1 (loc / offsets) scratch
__device__ __nv_bfloat16 g_t1hi[(size_t)NG*256];
__device__ __nv_bfloat16 g_t1lo[(size_t)NG*256];
__device__ __nv_bfloat16 g_u1hi[(size_t)NG*256];
__device__ __nv_bfloat16 g_u1lo[(size_t)NG*256];
__device__ float g_buf1[(size_t)NG*256];
__device__ float g_nh1[(size_t)NG*256];
__device__ __nv_bfloat16 g_col1h[(size_t)NG*KDIM];
__device__ __nv_bfloat16 g_col1l[(size_t)NG*KDIM];
__device__ float g_ws1[256];
// stream-2 (cls) scratch
__device__ __nv_bfloat16 g_t2hi[(size_t)NG*256];
__device__ __nv_bfloat16 g_t2lo[(size_t)NG*256];
__device__ float g_buf2[(size_t)NG*256];
__device__ float g_nh2[(size_t)NG*256];
__device__ __nv_bfloat16 g_col2h[(size_t)NG*KDIM];
__device__ __nv_bfloat16 g_col2l[(size_t)NG*KDIM];
__device__ float g_ws2[256];
__device__ float g_off1[OFFN];
__device__ float g_off2[OFFN];

// ---------------- PTX helpers ----------------
__device__ __forceinline__ uint32_t smem_u32(const void* p) {
    uint32_t a;
    asm("{ .reg .u64 t; cvta.to.shared.u64 t, %1; cvt.u32.u64 %0, t; }" : "=r"(a) : "l"(p));
    return a;
}
#define SWZ(o)   ((o) ^ (((o) >> 3) & 0x70))
#define SWZ64(o) ((o) ^ (((o) >> 3) & 0x30))

__device__ __forceinline__ void cp16(uint32_t dst, const void* src, int ss) {
    asm volatile("cp.async.cg.shared.global [%0], [%1], 16, %2;\n" :: "r"(dst), "l"(src), "r"(ss));
}
__device__ __forceinline__ void cp_commit() { asm volatile("cp.async.commit_group;\n" ::: "memory"); }
__device__ __forceinline__ void cp_wait0()  { asm volatile("cp.async.wait_group 0;\n" ::: "memory"); }
__device__ __forceinline__ void cp_wait1()  { asm volatile("cp.async.wait_group 1;\n" ::: "memory"); }

__device__ __forceinline__ void ldm4(uint32_t* r, uint32_t addr) {
    asm volatile("ldmatrix.sync.aligned.m8n8.x4.shared.b16 {%0,%1,%2,%3}, [%4];"
        : "=r"(r[0]), "=r"(r[1]), "=r"(r[2]), "=r"(r[3]) : "r"(addr));
}
__device__ __forceinline__ void mma16816(float* d, const uint32_t* a, const uint32_t* b) {
    asm volatile("mma.sync.aligned.m16n8k16.row.col.f32.bf16.bf16.f32 "
        "{%0,%1,%2,%3}, {%4,%5,%6,%7}, {%8,%9}, {%0,%1,%2,%3};"
        : "+f"(d[0]), "+f"(d[1]), "+f"(d[2]), "+f"(d[3])
        : "r"(a[0]), "r"(a[1]), "r"(a[2]), "r"(a[3]), "r"(b[0]), "r"(b[1]));
}

__device__ __forceinline__ unsigned short bfbits(float x) {
    __nv_bfloat16 h = __float2bfloat16(x);
    return *reinterpret_cast<unsigned short*>(&h);
}

// ---------------- shared epilogues ----------------
// EPI 0: NCHW float. EPI 1: NHWC bf16 hi/lo split planes (via smem transpose).
template<int IM>
__device__ __forceinline__ void epilogue_nchw(float acc[IM][4][4], float* out, int bstride,
                                              int M, int m0, int n0, int wm, int wn, int lane) {
    int b = n0 >> 12, ij0 = n0 & 4095;
    float* outb = out + (size_t)b * bstride + ij0;
#pragma unroll
    for (int im = 0; im < IM; im++) {
        int mrow = m0 + wm + im * 16 + (lane >> 2);
#pragma unroll
        for (int jn = 0; jn < 4; jn++) {
            int ncol = wn + jn * 8 + (lane & 3) * 2;
            if (mrow < M) {
                float2 v = make_float2(acc[im][jn][0], acc[im][jn][1]);
                *(float2*)(outb + (size_t)mrow * 4096 + ncol) = v;
            }
            if (mrow + 8 < M) {
                float2 v = make_float2(acc[im][jn][2], acc[im][jn][3]);
                *(float2*)(outb + (size_t)(mrow + 8) * 4096 + ncol) = v;
            }
        }
    }
}

// 512-thread CTA, 16 warps (wm in {0,64}, wn = (wid&7)*32), IM=4, tile 128m x 256n.
__device__ __forceinline__ void epilogue_split(float acc[4][4][4],
                                               __nv_bfloat16* ohi, __nv_bfloat16* olo,
                                               float* smemf, int m0, int n0,
                                               int tid, int wid, int wm, int wn, int lane) {
    for (int ch = 0; ch < 8; ch++) {
        __syncthreads();
        if ((wid & 7) == ch) {
#pragma unroll
            for (int im = 0; im < 4; im++) {
                int m = wm + im * 16 + (lane >> 2);
#pragma unroll
                for (int jn = 0; jn < 4; jn++) {
                    int nl = jn * 8 + (lane & 3) * 2;
                    smemf[m * 33 + nl] = acc[im][jn][0];
                    smemf[m * 33 + nl + 1] = acc[im][jn][1];
                    smemf[(m + 8) * 33 + nl] = acc[im][jn][2];
                    smemf[(m + 8) * 33 + nl + 1] = acc[im][jn][3];
                }
            }
        }
        __syncthreads();
        int p = tid >> 4;             // 0..31 pixel in chunk
        int cq = (tid & 15) * 8;      // 8 channels
        size_t base = (size_t)(n0 + ch * 32 + p) * 256 + m0 + cq;
        uint32_t hw[4], lw[4];
#pragma unroll
        for (int i = 0; i < 4; i++) {
            float v0 = smemf[(cq + 2 * i) * 33 + p];
            float v1 = smemf[(cq + 2 * i + 1) * 33 + p];
            unsigned short h0 = bfbits(v0), h1 = bfbits(v1);
            float r0 = v0 - __bfloat162float(*reinterpret_cast<__nv_bfloat16*>(&h0));
            float r1 = v1 - __bfloat162float(*reinterpret_cast<__nv_bfloat16*>(&h1));
            hw[i] = (uint32_t)h0 | ((uint32_t)h1 << 16);
            lw[i] = (uint32_t)bfbits(r0) | ((uint32_t)bfbits(r1) << 16);
        }
        *(uint4*)(ohi + base) = make_uint4(hw[0], hw[1], hw[2], hw[3]);
        *(uint4*)(olo + base) = make_uint4(lw[0], lw[1], lw[2], lw[3]);
    }
}

// ---------------- all-weights convert (coalesced, smem-staged) ----------------
struct W12 { const float* p[12]; int m[12]; };
__global__ __launch_bounds__(256) void wconv_all_k(W12 w,
                                                   __nv_bfloat16* __restrict__ hi,
                                                   __nv_bfloat16* __restrict__ lo) {
    __shared__ float rows[4][KDIM];
    int t = blockIdx.x >> 6;          // 12 tensors
    int rb = blockIdx.x & 63;         // 64 blocks of 4 rows
    int tid = threadIdx.x;
    int m0 = rb * 4;
    const float* src = w.p[t];
    int Mv = w.m[t];
    for (int i = tid; i < 4 * KDIM; i += 256) {
        int r = i / KDIM, k = i - r * KDIM;
        int m = m0 + r;
        rows[r][k] = (m < Mv) ? src[(size_t)m * KDIM + k] : 0.f;
    }
    __syncthreads();
    for (int i = tid; i < 4 * KDIM; i += 256) {
        int r = i / KDIM, k = i - r * KDIM;
        int kk = k >> 8, c = k & 255;
        float v = rows[r][c * 9 + kk];
        size_t dst = (size_t)t * PL + (size_t)(m0 + r) * KDIM + k;
        __nv_bfloat16 h = __float2bfloat16(v);
        hi[dst] = h;
        lo[dst] = __float2bfloat16(v - __bfloat162float(h));
    }
}

// ---------------- GN stats ----------------
__global__ __launch_bounds__(256) void gnstat_k(const float* __restrict__ in,
                                                float* __restrict__ ws) {
    int bg = blockIdx.x;
    int b = bg >> 5, g = bg & 31;
    int tid = threadIdx.x;
    const float4* p = (const float4*)(in + ((size_t)b * 256 + g * 8) * 4096);
    float s = 0.f, s2 = 0.f;
    for (int i = tid; i < 8192; i += 256) {
        float4 v = p[i];
        s += v.x + v.y + v.z + v.w;
        s2 += v.x * v.x + v.y * v.y + v.z * v.z + v.w * v.w;
    }
    __shared__ float sA[256], sB[256];
    sA[tid] = s; sB[tid] = s2;
    __syncthreads();
    for (int st = 128; st > 0; st >>= 1) {
        if (tid < st) { sA[tid] += sA[tid + st]; sB[tid] += sB[tid + st]; }
        __syncthreads();
    }
    if (tid == 0) {
        float mean = sA[0] * (1.f / 32768.f);
        float var = sB[0] * (1.f / 32768.f) - mean * mean;
        ws[bg * 2] = mean;
        ws[bg * 2 + 1] = rsqrtf(var + 1e-5f);
    }
}

// ---------------- NCHW fp32 -> (GN affine) -> NHWC hi/lo bf16 (+fp32) ----------------
__global__ void tsplit_k(const float* __restrict__ in,
                         __nv_bfloat16* __restrict__ hi, __nv_bfloat16* __restrict__ lo,
                         float* __restrict__ f32o,
                         const float* __restrict__ ws,
                         const float* __restrict__ gamma, const float* __restrict__ beta) {
    __shared__ float t[32][33];
    int b = blockIdx.z, hw0 = blockIdx.x * 32, c0 = blockIdx.y * 32;
    int tx = threadIdx.x, ty = threadIdx.y;
    const float* ip = in + (size_t)b * 256 * 4096;
    for (int r = ty; r < 32; r += 8)
        t[r][tx] = ip[(size_t)(c0 + r) * 4096 + hw0 + tx];
    __syncthreads();
    int ch = c0 + tx;
    float sc = 1.f, sh = 0.f;
    if (ws) {
        int bg = b * 32 + (ch >> 3);
        float mean = ws[bg * 2], rstd = ws[bg * 2 + 1];
        sc = rstd * gamma[ch];
        sh = beta[ch] - mean * sc;
    }
    for (int r = ty; r < 32; r += 8) {
        float v = t[tx][r] * sc + sh;
        size_t idx = (size_t)b * 4096 * 256 + (size_t)(hw0 + r) * 256 + ch;
        if (hi) {
            __nv_bfloat16 h = __float2bfloat16(v);
            hi[idx] = h;
            lo[idx] = __float2bfloat16(v - __bfloat162float(h));
        }
        if (f32o) f32o[idx] = v;
    }
}

// ---------------- slab-based implicit-conv GEMM ----------------
template<int MROWS, int NTHREADS, int EPI>
__global__ __launch_bounds__(NTHREADS, 1) void gemm_conv_k(
    const __nv_bfloat16* __restrict__ Ahi, const __nv_bfloat16* __restrict__ Alo,
    const __nv_bfloat16* __restrict__ Bhi, const __nv_bfloat16* __restrict__ Blo,
    float* __restrict__ out, __nv_bfloat16* __restrict__ ohi, __nv_bfloat16* __restrict__ olo,
    int M, int bstride) {
    constexpr int MW = NTHREADS / 256;
    constexpr int IM = MROWS / (MW * 16);
    constexpr int APL = MROWS * 64;
    constexpr int AST = 2 * APL;
    constexpr int SST = 2 * SPL;

    extern __shared__ char smx[];
    uint32_t smb = (smem_u32(smx) + 1023) & ~1023u;
    uint32_t aB = smb, sB = smb + 2 * AST;

    int tid = threadIdx.x;
    int lane = tid & 31;
    int wid = tid >> 5;
    int wm = (wid >> 3) * (IM * 16);
    int wn = (wid & 7) * 32;
    int n0 = blockIdx.x * 256;
    int m0 = blockIdx.y * MROWS;
    int b = n0 >> 12, ij0 = n0 & 4095;
    int i0 = ij0 >> 6;

    auto load_A = [&](int t, uint32_t dst) {
        int cg = t / 9, tap = t - cg * 9;
        int koff = tap * 256 + cg * 32;
#pragma unroll
        for (int idx = tid; idx < MROWS * 8; idx += NTHREADS) {
            int plane = idx >= MROWS * 4;
            int q = idx - plane * (MROWS * 4);
            int row = q >> 2, c16 = q & 3;
            const __nv_bfloat16* src =
                (plane ? Alo : Ahi) + (size_t)(m0 + row) * KDIM + koff + c16 * 8;
            cp16(dst + plane * APL + SWZ64(row * 64 + c16 * 16), src, 16);
        }
    };
    auto load_slab = [&](int cg, uint32_t dst) {
        for (int idx = tid; idx < 3168; idx += NTHREADS) {
            int plane = idx >= 1584;
            int q = idx - plane * 1584;
            int pix = q >> 2, c16 = q & 3;
            int sy = pix / 66, sx = pix - sy * 66;
            int y = i0 - 1 + sy, x = sx - 1;
            bool v = ((unsigned)y < 64u) && ((unsigned)x < 64u);
            int yy = v ? y : 0, xx = v ? x : 0;
            const __nv_bfloat16* src = (plane ? Blo : Bhi) +
                ((((size_t)b * 64 + yy) * 64 + xx) << 8) + cg * 32 + c16 * 8;
            cp16(dst + plane * SPL + SWZ64(pix * 64 + c16 * 16), src, v ? 16 : 0);
        }
    };

    float acc[IM][4][4];
#pragma unroll
    for (int im = 0; im < IM; im++)
#pragma unroll
        for (int jn = 0; jn < 4; jn++)
#pragma unroll
            for (int q = 0; q < 4; q++) acc[im][jn][q] = 0.f;

    int arow = lane & 15;
    int abyte = (lane >> 4) * 16;
    int mi = lane >> 3;
    int brow_off = (mi >> 1) * 8 + (lane & 7);
    int bbyte = (mi & 1) * 16;
    int b66[2];
#pragma unroll
    for (int jp = 0; jp < 2; jp++) {
        int rowb = wn + jp * 16 + brow_off;
        b66[jp] = (rowb >> 6) * 66 + (rowb & 63);
    }

    load_slab(0, sB);
    load_A(0, aB);
    cp_commit();

    for (int t = 0; t < 72; t++) {
        int cg = t / 9, tap = t - cg * 9;
        if (t + 1 < 72) {
            load_A(t + 1, aB + ((t + 1) & 1) * AST);
            if (tap == 4 && cg < 7) load_slab(cg + 1, sB + ((cg + 1) & 1) * SST);
            cp_commit();
            cp_wait1();
        } else {
            cp_wait0();
        }
        __syncthreads();

        uint32_t ab = aB + (t & 1) * AST;
        uint32_t sb = sB + (cg & 1) * SST;
        int kd = (tap * 11) >> 5;
        int tapoff = kd * 66 + (tap - kd * 3);
#pragma unroll
        for (int s = 0; s < 2; s++) {
            uint32_t bh[4][2], bl[4][2];
#pragma unroll
            for (int jp = 0; jp < 2; jp++) {
                int pix = b66[jp] + tapoff;
                uint32_t off = SWZ64(pix * 64 + s * 32 + bbyte);
                uint32_t r4[4];
                ldm4(r4, sb + off);
                bh[jp * 2][0] = r4[0]; bh[jp * 2][1] = r4[1];
                bh[jp * 2 + 1][0] = r4[2]; bh[jp * 2 + 1][1] = r4[3];
                ldm4(r4, sb + SPL + off);
                bl[jp * 2][0] = r4[0]; bl[jp * 2][1] = r4[1];
                bl[jp * 2 + 1][0] = r4[2]; bl[jp * 2 + 1][1] = r4[3];
            }
#pragma unroll
            for (int im = 0; im < IM; im++) {
                int rowa = wm + im * 16 + arow;
                uint32_t offa = SWZ64(rowa * 64 + s * 32 + abyte);
                uint32_t ah[4], al[4];
                ldm4(ah, ab + offa);
                ldm4(al, ab + APL + offa);
#pragma unroll
                for (int jn = 0; jn < 4; jn++) {
                    mma16816(acc[im][jn], ah, bh[jn]);
                    mma16816(acc[im][jn], ah, bl[jn]);
                    mma16816(acc[im][jn], al, bh[jn]);
                }
            }
        }
        __syncthreads();
    }

    if (EPI == 0) {
        epilogue_nchw<IM>(acc, out, bstride, M, m0, n0, wm, wn, lane);
    } else {
        epilogue_split(acc, ohi, olo, (float*)(size_t)(uintptr_t)smx + 0, m0, n0, tid, wid, wm, wn, lane);
    }
}

// ---------------- col-based GEMM for deform convs ----------------
template<int EPI>
__global__ __launch_bounds__(512, 1) void gemm_col_k(const __nv_bfloat16* __restrict__ Ahi,
                                                     const __nv_bfloat16* __restrict__ Alo,
                                                     const __nv_bfloat16* __restrict__ Bhi,
                                                     const __nv_bfloat16* __restrict__ Blo,
                                                     float* __restrict__ out,
                                                     __nv_bfloat16* __restrict__ ohi,
                                                     __nv_bfloat16* __restrict__ olo,
                                                     int M, int bstride) {
    extern __shared__ char smx[];
    uint32_t smb = (smem_u32(smx) + 1023) & ~1023u;
    int tid = threadIdx.x;
    int lane = tid & 31;
    int wid = tid >> 5;
    int wm = (wid >> 3) * 64;
    int wn = (wid & 7) * 32;
    int n0 = blockIdx.x * 256;
    int m0 = blockIdx.y * 128;

    auto load_stage = [&](int t, uint32_t sb) {
        int kk = t >> 2, cg = t & 3;
        int koff = kk * 256 + cg * 64;
#pragma unroll
        for (int qi = 0; qi < 12; qi++) {
            int q = qi * 512 + tid;
            if (qi < 4) {
                int plane = (q >> 10) & 1;
                int qq = q & 1023;
                int row = qq >> 3, c16 = qq & 7;
                const __nv_bfloat16* src =
                    (plane ? Alo : Ahi) + (size_t)(m0 + row) * KDIM + koff + c16 * 8;
                cp16(sb + plane * 16384 + SWZ(row * 128 + c16 * 16), src, 16);
            } else {
                int qb = q - 2048;
                int plane = qb >> 11;
                int qq = qb & 2047;
                int row = qq >> 3, c16 = qq & 7;
                const __nv_bfloat16* src =
                    (plane ? Blo : Bhi) + (size_t)(n0 + row) * KDIM + koff + c16 * 8;
                cp16(sb + 32768 + plane * 32768 + SWZ(row * 128 + c16 * 16), src, 16);
            }
        }
    };

    float acc[4][4][4];
#pragma unroll
    for (int im = 0; im < 4; im++)
#pragma unroll
        for (int jn = 0; jn < 4; jn++)
#pragma unroll
            for (int q = 0; q < 4; q++) acc[im][jn][q] = 0.f;

    load_stage(0, smb);
    cp_commit();

    int arow_off = (lane & 15);
    int abyte = (lane >> 4) * 16;
    int mi = lane >> 3;
    int brow_off = (mi >> 1) * 8 + (lane & 7);
    int bbyte = (mi & 1) * 16;

    for (int t = 0; t < 36; t++) {
        if (t + 1 < 36) {
            load_stage(t + 1, smb + ((t + 1) & 1) * 98304);
            cp_commit();
            cp_wait1();
        } else {
            cp_wait0();
        }
        __syncthreads();

        uint32_t sb = smb + (t & 1) * 98304;
        uint32_t ahB = sb, alB = sb + 16384, bhB = sb + 32768, blB = sb + 65536;
#pragma unroll
        for (int s = 0; s < 4; s++) {
            uint32_t bh[4][2], bl[4][2];
#pragma unroll
            for (int jp = 0; jp < 2; jp++) {
                int rowb = wn + jp * 16 + brow_off;
                uint32_t off = SWZ(rowb * 128 + s * 32 + bbyte);
                uint32_t r4[4];
                ldm4(r4, bhB + off);
                bh[jp * 2][0] = r4[0]; bh[jp * 2][1] = r4[1];
                bh[jp * 2 + 1][0] = r4[2]; bh[jp * 2 + 1][1] = r4[3];
                ldm4(r4, blB + off);
                bl[jp * 2][0] = r4[0]; bl[jp * 2][1] = r4[1];
                bl[jp * 2 + 1][0] = r4[2]; bl[jp * 2 + 1][1] = r4[3];
            }
#pragma unroll
            for (int im = 0; im < 4; im++) {
                int rowa = wm + im * 16 + arow_off;
                uint32_t off = SWZ(rowa * 128 + s * 32 + abyte);
                uint32_t ah[4], al[4];
                ldm4(ah, ahB + off);
                ldm4(al, alB + off);
#pragma unroll
                for (int jn = 0; jn < 4; jn++) {
                    mma16816(acc[im][jn], ah, bh[jn]);
                    mma16816(acc[im][jn], ah, bl[jn]);
                    mma16816(acc[im][jn], al, bh[jn]);
                }
            }
        }
        __syncthreads();
    }

    if (EPI == 0) {
        epilogue_nchw<4>(acc, out, bstride, M, m0, n0, wm, wn, lane);
    } else {
        epilogue_split(acc, ohi, olo, (float*)smx, m0, n0, tid, wid, wm, wn, lane);
    }
}

// ---------------- deformable bilinear gather -> bf16 hi/lo col planes ----------------
__global__ __launch_bounds__(256) void deform_col_k(const float* __restrict__ nhwc,
                                                    const float* __restrict__ off,
                                                    __nv_bfloat16* __restrict__ colh,
                                                    __nv_bfloat16* __restrict__ coll) {
    int warp = (blockIdx.x * 256 + threadIdx.x) >> 5;
    int lane = threadIdx.x & 31;
    if (warp >= NG) return;
    int n = warp;
    int b = n >> 12, ij = n & 4095, i = ij >> 6, j = ij & 63;
    const float* offb = off + (size_t)b * 18 * 4096 + ij;
#pragma unroll
    for (int k = 0; k < 9; k++) {
        float dy = offb[(size_t)(2 * k) << 12];
        float dx = offb[(size_t)(2 * k + 1) << 12];
        float y = dy + (float)(i - 1 + k / 3);
        float x = dx + (float)(j - 1 + k % 3);
        float y0f = floorf(y), x0f = floorf(x);
        int y0 = (int)y0f, x0 = (int)x0f;
        float wy = y - y0f, wx = x - x0f;
        bool vy0 = (unsigned)y0 < 64u;
        bool vy1 = (unsigned)(y0 + 1) < 64u;
        bool vx0 = (unsigned)x0 < 64u;
        bool vx1 = (unsigned)(x0 + 1) < 64u;
        float w00 = (vy0 && vx0) ? (1.f - wy) * (1.f - wx) : 0.f;
        float w01 = (vy0 && vx1) ? (1.f - wy) * wx : 0.f;
        float w10 = (vy1 && vx0) ? wy * (1.f - wx) : 0.f;
        float w11 = (vy1 && vx1) ? wy * wx : 0.f;
        int cy0 = min(max(y0, 0), 63), cy1 = min(max(y0 + 1, 0), 63);
        int cx0 = min(max(x0, 0), 63), cx1 = min(max(x0 + 1, 0), 63);
        const float* p00 = nhwc + (((size_t)b * 64 + cy0) * 64 + cx0) * 256;
        const float* p01 = nhwc + (((size_t)b * 64 + cy0) * 64 + cx1) * 256;
        const float* p10 = nhwc + (((size_t)b * 64 + cy1) * 64 + cx0) * 256;
        const float* p11 = nhwc + (((size_t)b * 64 + cy1) * 64 + cx1) * 256;
        __nv_bfloat16* ch = colh + (size_t)n * KDIM + k * 256;
        __nv_bfloat16* cl = coll + (size_t)n * KDIM + k * 256;
#pragma unroll
        for (int it = 0; it < 8; it++) {
            int c = lane + it * 32;
            float v = w00 * p00[c] + w01 * p01[c] + w10 * p10[c] + w11 * p11[c];
            __nv_bfloat16 h = __float2bfloat16(v);
            ch[c] = h;
            cl[c] = __float2bfloat16(v - __bfloat162float(h));
        }
    }
}

// ---------------- rep-points epilogue ----------------
__global__ __launch_bounds__(256) void reppoints_k(const float* __restrict__ off1,
                                                   const float* __restrict__ off2,
                                                   float* __restrict__ out) {
    int idx = blockIdx.x * 256 + threadIdx.x;
    if (idx >= OFFN) return;
    int rem = idx % 73728;
    int ch = rem >> 12;
    int ij = rem & 4095;
    int i = ij >> 6, j = ij & 63;
    int k = ch >> 1;
    float init = (ch & 1) ? (float)(j + (k % 3) - 1) : (float)(i + (k / 3) - 1);
    float r1 = init + off1[idx];
    out[idx] = r1;
    out[OFFN + idx] = r1 + off2[idx];
}

// ---------------- host orchestration (2-stream overlap) ----------------
extern "C" void kernel_launch(void* const* d_in, const int* in_sizes, int n_in,
                              void* d_out, int out_size) {
    const float* feature = (const float*)d_in[0];
    const float* loc_ws  = (const float*)d_in[1];
    const float* loc_g   = (const float*)d_in[2];
    const float* loc_b   = (const float*)d_in[3];
    const float* cls_ws  = (const float*)d_in[4];
    const float* cls_g   = (const float*)d_in[5];
    const float* cls_b   = (const float*)d_in[6];
    const float* pi_w    = (const float*)d_in[7];
    const float* pio_w   = (const float*)d_in[8];
    const float* prd_w   = (const float*)d_in[9];
    const float* pro_w   = (const float*)d_in[10];
    const float* cd_w    = (const float*)d_in[11];
    const float* co_w    = (const float*)d_in[12];
    float* out = (float*)d_out;

    static int init_done = 0;
    static cudaStream_t s1, s2;
    static cudaEvent_t evRoot, evW, evF, evOff1, evE1, evE2;
    if (!init_done) {
        cudaFuncSetAttribute(gemm_conv_k<128, 512, 0>, cudaFuncAttributeMaxDynamicSharedMemorySize, BIG_SMEM);
        cudaFuncSetAttribute(gemm_conv_k<128, 512, 1>, cudaFuncAttributeMaxDynamicSharedMemorySize, BIG_SMEM);
        cudaFuncSetAttribute(gemm_conv_k<32, 256, 0>, cudaFuncAttributeMaxDynamicSharedMemorySize, SMALL_SMEM);
        cudaFuncSetAttribute(gemm_col_k<0>, cudaFuncAttributeMaxDynamicSharedMemorySize, COL_SMEM);
        cudaFuncSetAttribute(gemm_col_k<1>, cudaFuncAttributeMaxDynamicSharedMemorySize, COL_SMEM);
        cudaStreamCreateWithFlags(&s1, cudaStreamNonBlocking);
        cudaStreamCreateWithFlags(&s2, cudaStreamNonBlocking);
        cudaEventCreateWithFlags(&evRoot, cudaEventDisableTiming);
        cudaEventCreateWithFlags(&evW, cudaEventDisableTiming);
        cudaEventCreateWithFlags(&evF, cudaEventDisableTiming);
        cudaEventCreateWithFlags(&evOff1, cudaEventDisableTiming);
        cudaEventCreateWithFlags(&evE1, cudaEventDisableTiming);
        cudaEventCreateWithFlags(&evE2, cudaEventDisableTiming);
        init_done = 1;
    }

    __nv_bfloat16 *wahi, *walo, *fhi, *flo;
    __nv_bfloat16 *t1hi, *t1lo, *u1hi, *u1lo, *col1h, *col1l, *t2hi, *t2lo, *col2h, *col2l;
    float *buf1, *buf2, *nh1, *nh2, *off1, *off2, *ws1, *ws2;
    cudaGetSymbolAddress((void**)&wahi,  g_wahi);
    cudaGetSymbolAddress((void**)&walo,  g_walo);
    cudaGetSymbolAddress((void**)&fhi,   g_fhi);
    cudaGetSymbolAddress((void**)&flo,   g_flo);
    cudaGetSymbolAddress((void**)&t1hi,  g_t1hi);
    cudaGetSymbolAddress((void**)&t1lo,  g_t1lo);
    cudaGetSymbolAddress((void**)&u1hi,  g_u1hi);
    cudaGetSymbolAddress((void**)&u1lo,  g_u1lo);
    cudaGetSymbolAddress((void**)&col1h, g_col1h);
    cudaGetSymbolAddress((void**)&col1l, g_col1l);
    cudaGetSymbolAddress((void**)&t2hi,  g_t2hi);
    cudaGetSymbolAddress((void**)&t2lo,  g_t2lo);
    cudaGetSymbolAddress((void**)&col2h, g_col2h);
    cudaGetSymbolAddress((void**)&col2l, g_col2l);
    cudaGetSymbolAddress((void**)&buf1,  g_buf1);
    cudaGetSymbolAddress((void**)&buf2,  g_buf2);
    cudaGetSymbolAddress((void**)&nh1,   g_nh1);
    cudaGetSymbolAddress((void**)&nh2,   g_nh2);
    cudaGetSymbolAddress((void**)&off1,  g_off1);
    cudaGetSymbolAddress((void**)&off2,  g_off2);
    cudaGetSymbolAddress((void**)&ws1,   g_ws1);
    cudaGetSymbolAddress((void**)&ws2,   g_ws2);

    W12 w12;
    w12.p[0] = loc_ws;           w12.m[0] = 256;
    w12.p[1] = loc_ws + WSZ;     w12.m[1] = 256;
    w12.p[2] = loc_ws + 2 * WSZ; w12.m[2] = 256;
    w12.p[3] = cls_ws;           w12.m[3] = 256;
    w12.p[4] = cls_ws + WSZ;     w12.m[4] = 256;
    w12.p[5] = cls_ws + 2 * WSZ; w12.m[5] = 256;
    w12.p[6] = pi_w;             w12.m[6] = 256;
    w12.p[7] = pio_w;            w12.m[7] = 18;
    w12.p[8] = prd_w;            w12.m[8] = 256;
    w12.p[9] = pro_w;            w12.m[9] = 18;
    w12.p[10] = cd_w;            w12.m[10] = 256;
    w12.p[11] = co_w;            w12.m[11] = 15;

    dim3 tgrid(128, 8, 4), tblk(32, 8);
    dim3 gBig(64, 2), gSmall(64, 1);

    // fork from the capturing (default) stream
    cudaEventRecord(evRoot, 0);
    cudaStreamWaitEvent(s1, evRoot, 0);
    cudaStreamWaitEvent(s2, evRoot, 0);

    wconv_all_k<<<768, 256, 0, s1>>>(w12, wahi, walo);
    cudaEventRecord(evW, s1);
    tsplit_k<<<tgrid, tblk, 0, s2>>>(feature, fhi, flo, nullptr, nullptr, nullptr, nullptr);
    cudaEventRecord(evF, s2);
    cudaStreamWaitEvent(s1, evF, 0);
    cudaStreamWaitEvent(s2, evW, 0);

    // ---- s1: loc subnet -> offset1 -> offset2 branch -> reppoints ----
    for (int l = 0; l < 3; l++) {
        gemm_conv_k<128, 512, 0><<<gBig, 512, BIG_SMEM, s1>>>(
            wahi + (size_t)l * PL, walo + (size_t)l * PL,
            l == 0 ? fhi : t1hi, l == 0 ? flo : t1lo, buf1, nullptr, nullptr, 256, 256 * 4096);
        gnstat_k<<<128, 256, 0, s1>>>(buf1, ws1);
        tsplit_k<<<tgrid, tblk, 0, s1>>>(buf1, t1hi, t1lo, l == 2 ? nh1 : nullptr,
                                         ws1, loc_g + l * 256, loc_b + l * 256);
    }
    // pi: split-epilogue -> u1 planes (no tsplit)
    gemm_conv_k<128, 512, 1><<<gBig, 512, BIG_SMEM, s1>>>(
        wahi + 6 * (size_t)PL, walo + 6 * (size_t)PL, t1hi, t1lo,
        nullptr, u1hi, u1lo, 256, 0);
    gemm_conv_k<32, 256, 0><<<gSmall, 256, SMALL_SMEM, s1>>>(
        wahi + 7 * (size_t)PL, walo + 7 * (size_t)PL, u1hi, u1lo,
        off1, nullptr, nullptr, 18, 18 * 4096);
    cudaEventRecord(evOff1, s1);

    deform_col_k<<<2048, 256, 0, s1>>>(nh1, off1, col1h, col1l);
    gemm_col_k<1><<<gBig, 512, COL_SMEM, s1>>>(
        wahi + 8 * (size_t)PL, walo + 8 * (size_t)PL, col1h, col1l,
        nullptr, t1hi, t1lo, 256, 0);
    gemm_conv_k<32, 256, 0><<<gSmall, 256, SMALL_SMEM, s1>>>(
        wahi + 9 * (size_t)PL, walo + 9 * (size_t)PL, t1hi, t1lo,
        off2, nullptr, nullptr, 18, 18 * 4096);
    reppoints_k<<<(OFFN + 255) / 256, 256, 0, s1>>>(off1, off2, out);
    cudaEventRecord(evE1, s1);

    // ---- s2: cls subnet -> classification branch ----
    for (int l = 0; l < 3; l++) {
        gemm_conv_k<128, 512, 0><<<gBig, 512, BIG_SMEM, s2>>>(
            wahi + (size_t)(3 + l) * PL, walo + (size_t)(3 + l) * PL,
            l == 0 ? fhi : t2hi, l == 0 ? flo : t2lo, buf2, nullptr, nullptr, 256, 256 * 4096);
        gnstat_k<<<128, 256, 0, s2>>>(buf2, ws2);
        tsplit_k<<<tgrid, tblk, 0, s2>>>(buf2, l == 2 ? nullptr : t2hi, l == 2 ? nullptr : t2lo,
                                         l == 2 ? nh2 : nullptr,
                                         ws2, cls_g + l * 256, cls_b + l * 256);
    }
    cudaStreamWaitEvent(s2, evOff1, 0);
    deform_col_k<<<2048, 256, 0, s2>>>(nh2, off1, col2h, col2l);
    gemm_col_k<1><<<gBig, 512, COL_SMEM, s2>>>(
        wahi + 10 * (size_t)PL, walo + 10 * (size_t)PL, col2h, col2l,
        nullptr, t2hi, t2lo, 256, 0);
    gemm_conv_k<32, 256, 0><<<gSmall, 256, SMALL_SMEM, s2>>>(
        wahi + 11 * (size_t)PL, walo + 11 * (size_t)PL, t2hi, t2lo,
        out + 2 * OFFN, nullptr, nullptr, 15, 15 * 4096);
    cudaEventRecord(evE2, s2);

    // join back into the capturing stream
    cudaStreamWaitEvent(0, evE1, 0);
    cudaStreamWaitEvent(0, evE2, 0);
}